// round 7
// baseline (speedup 1.0000x reference)
#include <cuda_runtime.h>
#include <cuda_bf16.h>
#include <cstdint>
#include <cmath>

// Problem constants
constexpr int Nn  = 2048;   // tokens
constexpr int Dk  = 1024;   // model dim
constexpr int Hh  = 16;     // q heads
constexpr int KVh = 4;      // kv heads
constexpr int DHd = 64;     // head dim
constexpr int Ee  = 8;      // experts
constexpr int Ff  = 2048;   // ffn dim
constexpr int CHc = 64;     // ctrl hidden
constexpr float EPS = 1e-6f;
constexpr float DT  = 0.1f;
constexpr float BASE_SCALE = 10.0f;

// ---------------- device scratch (static, allowed) ----------------
__device__ float g_h1[Nn * Dk];
__device__ float g_q[Nn * Hh * DHd];
__device__ float g_k[Nn * KVh * DHd];
__device__ float g_v[Nn * KVh * DHd];
__device__ float g_o[Nn * Hh * DHd];
__device__ float g_oproj[Nn * Dk];
__device__ float g_ctrl[Nn * CHc];
__device__ float g_co[Nn * 3 * Dk];
__device__ float g_hidden2[Nn * Dk];
__device__ float g_x2[Nn * Dk];
__device__ float g_mid[Nn * Ff];
__device__ int   g_counts[Ee];
__device__ int   g_list[Ee * Nn];

// ---------------- rmsnorm (float4 vectorized) ----------------
__global__ void rmsnorm_kernel(const float* __restrict__ x, const float* __restrict__ w,
                               float* __restrict__ y)
{
    int n = blockIdx.x;
    const float4* xr = (const float4*)(x + (size_t)n * Dk);
    const float4* wr = (const float4*)w;
    float4*       yr = (float4*)(y + (size_t)n * Dk);
    float s = 0.f;
    float4 v = xr[threadIdx.x];   // Dk/4 = 256 float4, 256 threads
    s = v.x * v.x + v.y * v.y + v.z * v.z + v.w * v.w;
    __shared__ float red[8];
    int lane = threadIdx.x & 31, wid = threadIdx.x >> 5;
    #pragma unroll
    for (int o = 16; o; o >>= 1) s += __shfl_xor_sync(0xffffffffu, s, o);
    if (lane == 0) red[wid] = s;
    __syncthreads();
    if (wid == 0) {
        float t = (lane < 8) ? red[lane] : 0.f;
        #pragma unroll
        for (int o = 4; o; o >>= 1) t += __shfl_xor_sync(0xffffffffu, t, o);
        if (lane == 0) red[0] = rsqrtf(t / Dk + EPS);
    }
    __syncthreads();
    float rms = red[0];
    float4 wv = wr[threadIdx.x];
    float4 out;
    out.x = v.x * rms * wv.x;
    out.y = v.y * rms * wv.y;
    out.z = v.z * rms * wv.z;
    out.w = v.w * rms * wv.w;
    yr[threadIdx.x] = out;
}

// ============================================================================
// 128x128x16 SGEMM core pieces (256 threads, 8x8 micro-tile, pipelined LDG)
// thread (tx=tid&15, ty=tid>>4) computes rows {i*16+ty}, cols {j*16+tx}
// ============================================================================

// ---------------- fused QKV: [q|k|v] = h1@W + mu_prev@W_mu ----------------
__global__ __launch_bounds__(256, 2)
void qkv128_kernel(const float* __restrict__ h1, const float* __restrict__ mu,
                   const float* __restrict__ wq, const float* __restrict__ wmq,
                   const float* __restrict__ wk, const float* __restrict__ wmk,
                   const float* __restrict__ wv, const float* __restrict__ wmv,
                   float* __restrict__ qo, float* __restrict__ ko, float* __restrict__ vo)
{
    __shared__ float As[16][128];
    __shared__ float Bs[16][128];
    int bx = blockIdx.x;   // 0..11
    const float *B0, *B1; float* C; int ldb, colbase;
    if (bx < 8)       { B0 = wq; B1 = wmq; C = qo; ldb = 1024; colbase = bx * 128; }
    else if (bx < 10) { B0 = wk; B1 = wmk; C = ko; ldb = 256;  colbase = (bx - 8) * 128; }
    else              { B0 = wv; B1 = wmv; C = vo; ldb = 256;  colbase = (bx - 10) * 128; }
    int row0 = blockIdx.y * 128;
    int tid = threadIdx.x;
    int tx = tid & 15, ty = tid >> 4;
    int rowA = tid >> 1, colA = (tid & 1) << 3;
    int rB0 = tid >> 5,        cB0 = (tid & 31) << 2;
    int rB1 = (tid + 256) >> 5, cB1 = cB0;
    float acc[8][8] = {};

    const int T = 2 * (Dk / 16);   // 128 tiles (2 passes)
    float4 a0, a1, b0, b1;
    // tile loader
    auto ldg = [&](int t, float4& la0, float4& la1, float4& lb0, float4& lb1) {
        int pass = t >> 6;
        int k0 = (t & 63) << 4;
        const float* Ap = pass ? mu : h1;
        const float* Bp = pass ? B1 : B0;
        const float* ar = Ap + (size_t)(row0 + rowA) * Dk + k0 + colA;
        la0 = *(const float4*)ar;
        la1 = *(const float4*)(ar + 4);
        lb0 = *(const float4*)&Bp[(size_t)(k0 + rB0) * ldb + colbase + cB0];
        lb1 = *(const float4*)&Bp[(size_t)(k0 + rB1) * ldb + colbase + cB1];
    };
    ldg(0, a0, a1, b0, b1);
    for (int t = 0; t < T; ++t) {
        __syncthreads();
        #pragma unroll
        for (int j = 0; j < 4; ++j) As[colA + j][rowA] = (&a0.x)[j];
        #pragma unroll
        for (int j = 0; j < 4; ++j) As[colA + 4 + j][rowA] = (&a1.x)[j];
        *(float4*)&Bs[rB0][cB0] = b0;
        *(float4*)&Bs[rB1][cB1] = b1;
        __syncthreads();
        int tn = (t + 1 < T) ? t + 1 : T - 1;
        ldg(tn, a0, a1, b0, b1);
        #pragma unroll
        for (int kk = 0; kk < 16; ++kk) {
            float a[8], b[8];
            #pragma unroll
            for (int i = 0; i < 8; i++) a[i] = As[kk][i * 16 + ty];
            #pragma unroll
            for (int j = 0; j < 8; j++) b[j] = Bs[kk][j * 16 + tx];
            #pragma unroll
            for (int i = 0; i < 8; i++)
                #pragma unroll
                for (int j = 0; j < 8; j++)
                    acc[i][j] += a[i] * b[j];
        }
    }
    #pragma unroll
    for (int i = 0; i < 8; i++) {
        int r = row0 + i * 16 + ty;
        #pragma unroll
        for (int j = 0; j < 8; j++)
            C[(size_t)r * ldb + colbase + j * 16 + tx] = acc[i][j];
    }
}

// ---------------- plain dense 128x128 GEMM: C = A@B (+bias) ----------------
__global__ __launch_bounds__(256, 2)
void gemm128_kernel(const float* __restrict__ A, const float* __restrict__ B,
                    const float* __restrict__ bias, float* __restrict__ C,
                    int M, int N, int K)
{
    __shared__ float As[16][128];
    __shared__ float Bs[16][128];
    int col0 = blockIdx.x * 128, row0 = blockIdx.y * 128;
    int tid = threadIdx.x;
    int tx = tid & 15, ty = tid >> 4;
    int rowA = tid >> 1, colA = (tid & 1) << 3;
    int rB0 = tid >> 5,        cB0 = (tid & 31) << 2;
    int rB1 = (tid + 256) >> 5;
    float acc[8][8] = {};

    const int T = K / 16;
    float4 a0, a1, b0, b1;
    auto ldg = [&](int t, float4& la0, float4& la1, float4& lb0, float4& lb1) {
        int k0 = t << 4;
        const float* ar = A + (size_t)(row0 + rowA) * K + k0 + colA;
        la0 = *(const float4*)ar;
        la1 = *(const float4*)(ar + 4);
        lb0 = *(const float4*)&B[(size_t)(k0 + rB0) * N + col0 + cB0];
        lb1 = *(const float4*)&B[(size_t)(k0 + rB1) * N + col0 + cB0];
    };
    ldg(0, a0, a1, b0, b1);
    for (int t = 0; t < T; ++t) {
        __syncthreads();
        #pragma unroll
        for (int j = 0; j < 4; ++j) As[colA + j][rowA] = (&a0.x)[j];
        #pragma unroll
        for (int j = 0; j < 4; ++j) As[colA + 4 + j][rowA] = (&a1.x)[j];
        *(float4*)&Bs[rB0][cB0] = b0;
        *(float4*)&Bs[rB1][cB0] = b1;
        __syncthreads();
        int tn = (t + 1 < T) ? t + 1 : T - 1;
        ldg(tn, a0, a1, b0, b1);
        #pragma unroll
        for (int kk = 0; kk < 16; ++kk) {
            float a[8], b[8];
            #pragma unroll
            for (int i = 0; i < 8; i++) a[i] = As[kk][i * 16 + ty];
            #pragma unroll
            for (int j = 0; j < 8; j++) b[j] = Bs[kk][j * 16 + tx];
            #pragma unroll
            for (int i = 0; i < 8; i++)
                #pragma unroll
                for (int j = 0; j < 8; j++)
                    acc[i][j] += a[i] * b[j];
        }
    }
    #pragma unroll
    for (int i = 0; i < 8; i++) {
        int r = row0 + i * 16 + ty;
        #pragma unroll
        for (int j = 0; j < 8; j++) {
            int c = col0 + j * 16 + tx;
            float v = acc[i][j];
            if (bias) v += bias[c];
            C[(size_t)r * N + c] = v;
        }
    }
}

// ---------------- old 64x64 GEMM (kept for ctrl_in: N=64) ----------------
template<int ACT, bool DUAL>
__global__ void gemm64_kernel(const float* __restrict__ A, const float* __restrict__ B,
                              const float* __restrict__ A2, const float* __restrict__ B2,
                              const float* __restrict__ bias, float* __restrict__ C,
                              int M, int N, int K)
{
    __shared__ float As[64][16];
    __shared__ float Bs[16][64];
    int tid = threadIdx.x;
    int tx = tid & 15, ty = tid >> 4;
    int row0 = blockIdx.y * 64, col0 = blockIdx.x * 64;
    float acc[4][4] = {};

    int npass = DUAL ? 2 : 1;
    for (int pass = 0; pass < npass; ++pass) {
        const float* Ap = pass ? A2 : A;
        const float* Bp = pass ? B2 : B;
        for (int k0 = 0; k0 < K; k0 += 16) {
            #pragma unroll
            for (int i = tid; i < 64 * 16; i += 256) {
                int r = i >> 4, c = i & 15;
                As[r][c] = Ap[(size_t)(row0 + r) * K + k0 + c];
            }
            #pragma unroll
            for (int i = tid; i < 16 * 64; i += 256) {
                int r = i >> 6, c = i & 63;
                Bs[r][c] = Bp[(size_t)(k0 + r) * N + col0 + c];
            }
            __syncthreads();
            #pragma unroll
            for (int kk = 0; kk < 16; ++kk) {
                float a[4], b[4];
                #pragma unroll
                for (int i = 0; i < 4; i++) a[i] = As[ty * 4 + i][kk];
                #pragma unroll
                for (int j = 0; j < 4; j++) b[j] = Bs[kk][tx * 4 + j];
                #pragma unroll
                for (int i = 0; i < 4; i++)
                    #pragma unroll
                    for (int j = 0; j < 4; j++)
                        acc[i][j] += a[i] * b[j];
            }
            __syncthreads();
        }
    }
    #pragma unroll
    for (int i = 0; i < 4; i++) {
        int r = row0 + ty * 4 + i;
        #pragma unroll
        for (int j = 0; j < 4; j++) {
            int c = col0 + tx * 4 + j;
            float v = acc[i][j];
            if (bias) v += bias[c];
            if (ACT == 1) v = v / (1.f + expf(-v));   // silu
            C[(size_t)r * N + c] = v;
        }
    }
}

// ---------------- q/k rmsnorm + rope ----------------
__global__ void qknorm_rope_kernel(float* __restrict__ q, float* __restrict__ k,
                                   const int* __restrict__ positions,
                                   const float* __restrict__ qw, const float* __restrict__ kw)
{
    int n = blockIdx.x;
    int hh = blockIdx.y;   // 0..H+KV-1
    float* x; const float* w;
    if (hh < Hh) { x = q + ((size_t)n * Hh + hh) * DHd; w = qw; }
    else         { x = k + ((size_t)n * KVh + (hh - Hh)) * DHd; w = kw; }
    int lane = threadIdx.x;  // 0..31
    float x1 = x[lane], x2 = x[lane + 32];
    float s = x1 * x1 + x2 * x2;
    #pragma unroll
    for (int o = 16; o; o >>= 1) s += __shfl_xor_sync(0xffffffffu, s, o);
    float rms = rsqrtf(s / 64.f + EPS);
    float v1 = x1 * rms * w[lane];
    float v2 = x2 * rms * w[lane + 32];
    float inv = (float)exp(-(2.0 * (double)lane / 64.0) * log(10000.0));
    float ang = (float)positions[n] * inv;
    float c = cosf(ang), sn = sinf(ang);
    x[lane]      = v1 * c - v2 * sn;
    x[lane + 32] = v2 * c + v1 * sn;
}

// ---------------- flash-style attention (fp32, static smem <=48KB) ----------------
__global__ void attn_kernel(const float* __restrict__ q, const float* __restrict__ k,
                            const float* __restrict__ v, float* __restrict__ o)
{
    __shared__ float Qs[32][64];
    __shared__ float KVs[64][65];
    __shared__ float Ss[32][65];
    __shared__ float mrow[32], lrow[32], crow[32];

    int h = blockIdx.y;
    int kvh = h >> 2;          // H/KV = 4
    int q0 = blockIdx.x * 32;
    int tid = threadIdx.x;
    int tx = tid & 63, ty = tid >> 6;

    for (int r = ty; r < 32; r += 4)
        Qs[r][tx] = q[((size_t)(q0 + r) * Hh + h) * DHd + tx];
    if (tid < 32) { mrow[tid] = -1e30f; lrow[tid] = 0.f; }
    float acc[8];
    #pragma unroll
    for (int i = 0; i < 8; i++) acc[i] = 0.f;
    __syncthreads();

    for (int kt = 0; kt < Nn / 64; ++kt) {
        int kb = kt * 64;
        for (int r = ty; r < 64; r += 4)
            KVs[r][tx] = k[((size_t)(kb + r) * KVh + kvh) * DHd + tx];
        __syncthreads();
        #pragma unroll
        for (int i = 0; i < 8; ++i) {
            int r = ty + i * 4;
            float s = 0.f;
            #pragma unroll
            for (int d = 0; d < 64; ++d) s += Qs[r][d] * KVs[tx][d];
            Ss[r][tx] = s * 0.125f;   // 1/sqrt(64)
        }
        __syncthreads();
        if (tid < 32) {
            int r = tid;
            float mx = -1e30f;
            #pragma unroll 8
            for (int c = 0; c < 64; ++c) mx = fmaxf(mx, Ss[r][c]);
            float mnew = fmaxf(mrow[r], mx);
            float corr = expf(mrow[r] - mnew);
            float lsum = 0.f;
            #pragma unroll 8
            for (int c = 0; c < 64; ++c) {
                float p = expf(Ss[r][c] - mnew);
                Ss[r][c] = p; lsum += p;
            }
            lrow[r] = lrow[r] * corr + lsum;
            mrow[r] = mnew;
            crow[r] = corr;
        }
        __syncthreads();
        for (int r = ty; r < 64; r += 4)
            KVs[r][tx] = v[((size_t)(kb + r) * KVh + kvh) * DHd + tx];
        __syncthreads();
        #pragma unroll
        for (int i = 0; i < 8; ++i) {
            int r = ty + i * 4;
            float s = 0.f;
            #pragma unroll
            for (int c = 0; c < 64; ++c) s += Ss[r][c] * KVs[c][tx];
            acc[i] = acc[i] * crow[r] + s;
        }
        __syncthreads();
    }
    #pragma unroll
    for (int i = 0; i < 8; ++i) {
        int r = ty + i * 4;
        o[((size_t)(q0 + r) * Hh + h) * DHd + tx] = acc[i] / lrow[r];
    }
}

// ---------------- dynamics (elementwise, float4) ----------------
__global__ void dynamics_kernel(const float4* __restrict__ hidden_in,
                                const float4* __restrict__ velocity,
                                const float4* __restrict__ oproj,
                                const float4* __restrict__ mu,
                                const float* __restrict__ co,
                                float4* __restrict__ v_out,
                                float4* __restrict__ hidden2)
{
    int idx = blockIdx.x * blockDim.x + threadIdx.x;   // float4 index
    if (idx >= Nn * Dk / 4) return;
    int n = idx / (Dk / 4), c4 = idx - n * (Dk / 4);
    const float4* cr = (const float4*)(co + (size_t)n * 3 * Dk);
    float4 a_raw  = cr[c4];
    float4 b_raw  = cr[Dk / 4 + c4];
    float4 gt_raw = cr[2 * Dk / 4 + c4];
    float4 ov  = oproj[idx];
    float4 muv = mu[idx];
    float4 vel = velocity[idx];
    float4 hin = hidden_in[idx];
    float4 vn, h2;
    #pragma unroll
    for (int j = 0; j < 4; ++j) {
        float ar = (&a_raw.x)[j], br = (&b_raw.x)[j], gr = (&gt_raw.x)[j];
        float alpha = 1.f / (1.f + expf(-ar));
        float sp = (br > 20.f) ? br : log1pf(expf(br));
        float beta = fminf(sp, 2.f);
        float gate = 1.f / (1.f + expf(-gr));
        float o = (&ov.x)[j];
        float err = o - (&muv.x)[j];
        float vv = alpha * (&vel.x)[j] - beta * err;
        vv = fminf(fmaxf(vv, -10.f), 10.f);
        (&vn.x)[j] = vv;
        (&h2.x)[j] = (&hin.x)[j] + o + DT * gate * vv;
    }
    v_out[idx] = vn;
    hidden2[idx] = h2;
}

// ---------------- router ----------------
__global__ void reset_counts_kernel()
{
    if (threadIdx.x < Ee) g_counts[threadIdx.x] = 0;
}

__global__ void router_kernel(const float* __restrict__ mu, const float* __restrict__ W,
                              const int* __restrict__ token_ids)
{
    int gwarp = (blockIdx.x * blockDim.x + threadIdx.x) >> 5;
    int lane = threadIdx.x & 31;
    if (gwarp >= Nn) return;
    float acc[Ee] = {};
    const float* m = mu + (size_t)gwarp * Dk;
    for (int d = lane; d < Dk; d += 32) {
        float mv = m[d];
        #pragma unroll
        for (int e = 0; e < Ee; ++e) acc[e] += mv * W[d * Ee + e];
    }
    #pragma unroll
    for (int o = 16; o; o >>= 1)
        #pragma unroll
        for (int e = 0; e < Ee; ++e) acc[e] += __shfl_xor_sync(0xffffffffu, acc[e], o);
    if (lane == 0) {
        int base = token_ids[gwarp] % Ee;
        int best = 0; float bv = -1e30f;
        #pragma unroll
        for (int e = 0; e < Ee; ++e) {
            float vv = acc[e] + (e == base ? BASE_SCALE : 0.f);
            if (vv > bv) { bv = vv; best = e; }
        }
        int pos = atomicAdd(&g_counts[best], 1);
        g_list[best * Nn + pos] = gwarp;
    }
}

// ---------------- MoE gate/up fused (gathered, BM=128,BN=64, dual acc) ------
// writes Mid[t][c] = silu(g)*u directly
__global__ __launch_bounds__(256, 2)
void moe_gateup128_kernel(const float* __restrict__ X,
                          const float* __restrict__ Wg,
                          const float* __restrict__ Wu,
                          float* __restrict__ Mid)
{
    int e = blockIdx.z;
    int cnt = g_counts[e];
    int row0 = blockIdx.y * 128;
    if (row0 >= cnt) return;
    int col0 = blockIdx.x * 64;
    const float* Bg = Wg + (size_t)e * Dk * Ff;
    const float* Bu = Wu + (size_t)e * Dk * Ff;

    __shared__ float As[16][128];
    __shared__ float Bsg[16][64];
    __shared__ float Bsu[16][64];
    __shared__ int toks[128];
    int tid = threadIdx.x;
    int tx = tid & 15, ty = tid >> 4;
    int rowA = tid >> 1, colA = (tid & 1) << 3;
    int rB = tid >> 4, cB = (tid & 15) << 2;
    if (tid < 128)
        toks[tid] = (row0 + tid < cnt) ? g_list[e * Nn + row0 + tid] : -1;
    __syncthreads();
    int myTok = toks[rowA];

    float accg[8][4] = {}, accu[8][4] = {};
    const int T = Dk / 16;
    float4 a0, a1, bg4, bu4;
    auto ldg = [&](int t, float4& la0, float4& la1, float4& lg, float4& lu) {
        int k0 = t << 4;
        if (myTok >= 0) {
            const float* ar = X + (size_t)myTok * Dk + k0 + colA;
            la0 = *(const float4*)ar;
            la1 = *(const float4*)(ar + 4);
        } else {
            la0 = make_float4(0, 0, 0, 0);
            la1 = make_float4(0, 0, 0, 0);
        }
        lg = *(const float4*)&Bg[(size_t)(k0 + rB) * Ff + col0 + cB];
        lu = *(const float4*)&Bu[(size_t)(k0 + rB) * Ff + col0 + cB];
    };
    ldg(0, a0, a1, bg4, bu4);
    for (int t = 0; t < T; ++t) {
        __syncthreads();
        #pragma unroll
        for (int j = 0; j < 4; ++j) As[colA + j][rowA] = (&a0.x)[j];
        #pragma unroll
        for (int j = 0; j < 4; ++j) As[colA + 4 + j][rowA] = (&a1.x)[j];
        *(float4*)&Bsg[rB][cB] = bg4;
        *(float4*)&Bsu[rB][cB] = bu4;
        __syncthreads();
        int tn = (t + 1 < T) ? t + 1 : T - 1;
        ldg(tn, a0, a1, bg4, bu4);
        #pragma unroll
        for (int kk = 0; kk < 16; ++kk) {
            float a[8], bg[4], bu[4];
            #pragma unroll
            for (int i = 0; i < 8; i++) a[i] = As[kk][i * 16 + ty];
            #pragma unroll
            for (int j = 0; j < 4; j++) { bg[j] = Bsg[kk][j * 16 + tx]; bu[j] = Bsu[kk][j * 16 + tx]; }
            #pragma unroll
            for (int i = 0; i < 8; i++)
                #pragma unroll
                for (int j = 0; j < 4; j++) {
                    accg[i][j] += a[i] * bg[j];
                    accu[i][j] += a[i] * bu[j];
                }
        }
    }
    #pragma unroll
    for (int i = 0; i < 8; i++) {
        int t = toks[i * 16 + ty];
        if (t < 0) continue;
        #pragma unroll
        for (int j = 0; j < 4; j++) {
            int c = col0 + j * 16 + tx;
            float g = accg[i][j];
            float sg = g / (1.f + expf(-g));
            Mid[(size_t)t * Ff + c] = sg * accu[i][j];
        }
    }
}

// ---------------- MoE down (gathered 128x128) + residual ----------------
__global__ __launch_bounds__(256, 2)
void moe_down128_kernel(const float* __restrict__ Mid,
                        const float* __restrict__ Wd,
                        const float* __restrict__ res,
                        float* __restrict__ Out)
{
    int e = blockIdx.z;
    int cnt = g_counts[e];
    int row0 = blockIdx.y * 128;
    if (row0 >= cnt) return;
    int col0 = blockIdx.x * 128;
    const float* Bp = Wd + (size_t)e * Ff * Dk;

    __shared__ float As[16][128];
    __shared__ float Bs[16][128];
    __shared__ int toks[128];
    int tid = threadIdx.x;
    int tx = tid & 15, ty = tid >> 4;
    int rowA = tid >> 1, colA = (tid & 1) << 3;
    int rB0 = tid >> 5, cB0 = (tid & 31) << 2;
    int rB1 = (tid + 256) >> 5;
    if (tid < 128)
        toks[tid] = (row0 + tid < cnt) ? g_list[e * Nn + row0 + tid] : -1;
    __syncthreads();
    int myTok = toks[rowA];

    float acc[8][8] = {};
    const int T = Ff / 16;
    float4 a0, a1, b0, b1;
    auto ldg = [&](int t, float4& la0, float4& la1, float4& lb0, float4& lb1) {
        int k0 = t << 4;
        if (myTok >= 0) {
            const float* ar = Mid + (size_t)myTok * Ff + k0 + colA;
            la0 = *(const float4*)ar;
            la1 = *(const float4*)(ar + 4);
        } else {
            la0 = make_float4(0, 0, 0, 0);
            la1 = make_float4(0, 0, 0, 0);
        }
        lb0 = *(const float4*)&Bp[(size_t)(k0 + rB0) * Dk + col0 + cB0];
        lb1 = *(const float4*)&Bp[(size_t)(k0 + rB1) * Dk + col0 + cB0];
    };
    ldg(0, a0, a1, b0, b1);
    for (int t = 0; t < T; ++t) {
        __syncthreads();
        #pragma unroll
        for (int j = 0; j < 4; ++j) As[colA + j][rowA] = (&a0.x)[j];
        #pragma unroll
        for (int j = 0; j < 4; ++j) As[colA + 4 + j][rowA] = (&a1.x)[j];
        *(float4*)&Bs[rB0][cB0] = b0;
        *(float4*)&Bs[rB1][cB0] = b1;
        __syncthreads();
        int tn = (t + 1 < T) ? t + 1 : T - 1;
        ldg(tn, a0, a1, b0, b1);
        #pragma unroll
        for (int kk = 0; kk < 16; ++kk) {
            float a[8], b[8];
            #pragma unroll
            for (int i = 0; i < 8; i++) a[i] = As[kk][i * 16 + ty];
            #pragma unroll
            for (int j = 0; j < 8; j++) b[j] = Bs[kk][j * 16 + tx];
            #pragma unroll
            for (int i = 0; i < 8; i++)
                #pragma unroll
                for (int j = 0; j < 8; j++)
                    acc[i][j] += a[i] * b[j];
        }
    }
    #pragma unroll
    for (int i = 0; i < 8; i++) {
        int t = toks[i * 16 + ty];
        if (t < 0) continue;
        #pragma unroll
        for (int j = 0; j < 8; j++) {
            int c = col0 + j * 16 + tx;
            Out[(size_t)t * Dk + c] = res[(size_t)t * Dk + c] + acc[i][j];
        }
    }
}

// ---------------- launch ----------------
static float* sym(const void* s)
{
    void* p = nullptr;
    cudaGetSymbolAddress(&p, s);
    return (float*)p;
}

extern "C" void kernel_launch(void* const* d_in, const int* in_sizes, int n_in,
                              void* d_out, int out_size)
{
    const float* hidden        = (const float*)d_in[0];
    const int*   positions     = (const int*)  d_in[1];
    const float* velocity      = (const float*)d_in[2];
    const int*   token_ids     = (const int*)  d_in[3];
    const float* mu_prev       = (const float*)d_in[4];
    const float* ln1_w         = (const float*)d_in[5];
    const float* ln2_w         = (const float*)d_in[6];
    const float* wq            = (const float*)d_in[7];
    const float* wk            = (const float*)d_in[8];
    const float* wv            = (const float*)d_in[9];
    const float* wo            = (const float*)d_in[10];
    const float* w_mu_q        = (const float*)d_in[11];
    const float* w_mu_k        = (const float*)d_in[12];
    const float* w_mu_v        = (const float*)d_in[13];
    const float* qnorm_w       = (const float*)d_in[14];
    const float* knorm_w       = (const float*)d_in[15];
    const float* dyn_mu        = (const float*)d_in[16];
    const float* dyn_mu_proj_w = (const float*)d_in[17];
    const float* ctrl_in_w     = (const float*)d_in[18];
    const float* ctrl_in_b     = (const float*)d_in[19];
    const float* ctrl_out_w    = (const float*)d_in[20];
    const float* ctrl_out_b    = (const float*)d_in[21];
    const float* mu_router_w   = (const float*)d_in[22];
    const float* w_gate        = (const float*)d_in[23];
    const float* w_up          = (const float*)d_in[24];
    const float* w_down        = (const float*)d_in[25];

    float* out_hidden = (float*)d_out;
    float* out_v      = out_hidden + (size_t)Nn * Dk;
    float* out_mu     = out_v + (size_t)Nn * Dk;

    float* h1   = sym(g_h1);
    float* qb   = sym(g_q);
    float* kb   = sym(g_k);
    float* vb   = sym(g_v);
    float* ob   = sym(g_o);
    float* op   = sym(g_oproj);
    float* ctrl = sym(g_ctrl);
    float* co   = sym(g_co);
    float* h2   = sym(g_hidden2);
    float* x2   = sym(g_x2);
    float* mid  = sym(g_mid);

    // 1) rmsnorm1
    rmsnorm_kernel<<<Nn, 256>>>(hidden, ln1_w, h1);

    // 2) fused QKV = h1@W + mu_prev@W_mu  (one launch, 12x16 = 192 CTAs)
    qkv128_kernel<<<dim3(12, Nn / 128), 256>>>(h1, mu_prev, wq, w_mu_q, wk, w_mu_k,
                                               wv, w_mu_v, qb, kb, vb);

    // 3) q/k norm + rope (in place)
    qknorm_rope_kernel<<<dim3(Nn, Hh + KVh), 32>>>(qb, kb, positions, qnorm_w, knorm_w);

    // 4) attention (static smem, 32-row q tiles)
    attn_kernel<<<dim3(Nn / 32, Hh), 256>>>(qb, kb, vb, ob);

    // 5) o-proj
    gemm128_kernel<<<dim3(Dk / 128, Nn / 128), 256>>>(ob, wo, nullptr, op, Nn, Dk, Hh * DHd);

    // 6) mu_cur = dyn_mu + oproj @ dyn_mu_proj_w  (written directly to output)
    gemm128_kernel<<<dim3(Dk / 128, Nn / 128), 256>>>(op, dyn_mu_proj_w, dyn_mu, out_mu, Nn, Dk, Dk);

    // 7) ctrl = silu([o, velocity] @ ctrl_in_w + b)   (N=64 -> 64-wide gemm)
    gemm64_kernel<1, true><<<dim3(CHc / 64, Nn / 64), 256>>>(op, ctrl_in_w, velocity,
        ctrl_in_w + (size_t)Dk * CHc, ctrl_in_b, ctrl, Nn, CHc, Dk);

    // 8) co = ctrl @ ctrl_out_w + b
    gemm128_kernel<<<dim3(3 * Dk / 128, Nn / 128), 256>>>(ctrl, ctrl_out_w, ctrl_out_b, co, Nn, 3 * Dk, CHc);

    // 9) dynamics: v_next (output), hidden2
    dynamics_kernel<<<(Nn * Dk / 4 + 255) / 256, 256>>>((const float4*)hidden, (const float4*)velocity,
                                                        (const float4*)op, (const float4*)out_mu, co,
                                                        (float4*)out_v, (float4*)h2);

    // 10) rmsnorm2
    rmsnorm_kernel<<<Nn, 256>>>(h2, ln2_w, x2);

    // 11) router
    reset_counts_kernel<<<1, 32>>>();
    router_kernel<<<(Nn * 32 + 255) / 256, 256>>>(out_mu, mu_router_w, token_ids);

    // 12) MoE gate/up fused -> Mid = silu(g)*u
    moe_gateup128_kernel<<<dim3(Ff / 64, Nn / 128, Ee), 256>>>(x2, w_gate, w_up, mid);

    // 13) MoE down + residual -> final hidden (output)
    moe_down128_kernel<<<dim3(Dk / 128, Nn / 128, Ee), 256>>>(mid, w_down, h2, out_hidden);
}

// round 8
// speedup vs baseline: 2.0432x; 2.0432x over previous
#include <cuda_runtime.h>
#include <cuda_bf16.h>
#include <cstdint>
#include <cmath>

// Problem constants
constexpr int Nn  = 2048;   // tokens
constexpr int Dk  = 1024;   // model dim
constexpr int Hh  = 16;     // q heads
constexpr int KVh = 4;      // kv heads
constexpr int DHd = 64;     // head dim
constexpr int Ee  = 8;      // experts
constexpr int Ff  = 2048;   // ffn dim
constexpr int CHc = 64;     // ctrl hidden
constexpr float EPS = 1e-6f;
constexpr float DT  = 0.1f;
constexpr float BASE_SCALE = 10.0f;

// ---------------- device scratch (static, allowed) ----------------
__device__ float g_h1[Nn * Dk];
__device__ float g_q[Nn * Hh * DHd];
__device__ float g_k[Nn * KVh * DHd];
__device__ float g_v[Nn * KVh * DHd];
__device__ float g_o[Nn * Hh * DHd];
__device__ float g_oproj[Nn * Dk];
__device__ float g_ctrl[Nn * CHc];
__device__ float g_co[Nn * 3 * Dk];
__device__ float g_hidden2[Nn * Dk];
__device__ float g_x2[Nn * Dk];
__device__ float g_midg[Nn * Ff];
__device__ float g_midu[Nn * Ff];
__device__ float g_mid[Nn * Ff];
__device__ int   g_counts[Ee];
__device__ int   g_list[Ee * Nn];

// ---------------- tf32 helpers ----------------
__device__ __forceinline__ uint32_t cvt_tf32(float x) {
    uint32_t r;
    asm("cvt.rna.tf32.f32 %0, %1;" : "=r"(r) : "f"(x));
    return r;
}

__device__ __forceinline__ void mma_tf32(float c[4],
    uint32_t a0, uint32_t a1, uint32_t a2, uint32_t a3,
    uint32_t b0, uint32_t b1)
{
    asm volatile("mma.sync.aligned.m16n8k8.row.col.f32.tf32.tf32.f32 "
        "{%0,%1,%2,%3}, {%4,%5,%6,%7}, {%8,%9}, {%0,%1,%2,%3};"
        : "+f"(c[0]), "+f"(c[1]), "+f"(c[2]), "+f"(c[3])
        : "r"(a0), "r"(a1), "r"(a2), "r"(a3), "r"(b0), "r"(b1));
}

// ============================================================================
// Unified tf32 tensor-core GEMM: C[M,N] = A@B (+ A2@B2) (+bias) (+res)
// BM=BN=128, BK=16, 256 threads (8 warps), warp tile 64x32 (4x4 m16n8k8).
// GATHER: A rows via g_list/g_counts[blockIdx.z], B += e*K*N, C scatter.
// ============================================================================
template<bool GATHER, bool DUAL, bool RES>
__global__ __launch_bounds__(256, 1)
void mma_gemm_kernel(const float* __restrict__ A, const float* __restrict__ Bw,
                     const float* __restrict__ A2, const float* __restrict__ B2,
                     const float* __restrict__ bias, const float* __restrict__ res,
                     float* __restrict__ C, int N, int K, int lda, int ldc)
{
    __shared__ uint32_t As[16][136];
    __shared__ uint32_t Bs[16][136];
    __shared__ int toks[128];

    const float* B = Bw;
    int row0 = blockIdx.y * 128;
    if (GATHER) {
        int e = blockIdx.z;
        int cnt = g_counts[e];
        if (row0 >= cnt) return;
        B += (size_t)e * K * N;
        if (threadIdx.x < 128) {
            int idx = row0 + threadIdx.x;
            toks[threadIdx.x] = (idx < cnt) ? g_list[e * Nn + idx] : -1;
        }
        __syncthreads();
    }
    int col0 = blockIdx.x * 128;
    int tid  = threadIdx.x;
    int lane = tid & 31, warp = tid >> 5;
    int grp = lane >> 2, tig = lane & 3;
    int wm = (warp >> 2) * 64;     // warp M offset
    int wn = (warp & 3) * 32;      // warp N offset

    int rowA = tid >> 1, colA = (tid & 1) << 3;    // A: 8 floats / thread
    int rB = tid >> 5,  cB = (tid & 31) << 2;      // B: 2 x float4 / thread

    long aRow = GATHER ? (long)toks[rowA] : (long)(row0 + rowA);

    float c[4][4][4];
    #pragma unroll
    for (int i = 0; i < 4; i++)
        #pragma unroll
        for (int j = 0; j < 4; j++)
            #pragma unroll
            for (int l = 0; l < 4; l++) c[i][j][l] = 0.f;

    const int TK = K / 16;
    const int T = (DUAL ? 2 : 1) * TK;
    float4 pa0, pa1, pb0, pb1;
    auto ldg = [&](int t) {
        int pass = DUAL ? (t >= TK) : 0;
        int k0 = (pass ? t - TK : t) << 4;
        const float* Ap = pass ? A2 : A;
        const float* Bp = pass ? B2 : B;
        if (!GATHER || aRow >= 0) {
            const float* ar = Ap + (size_t)aRow * lda + k0 + colA;
            pa0 = *(const float4*)ar;
            pa1 = *(const float4*)(ar + 4);
        } else {
            pa0 = make_float4(0, 0, 0, 0);
            pa1 = make_float4(0, 0, 0, 0);
        }
        pb0 = *(const float4*)&Bp[(size_t)(k0 + rB) * N + col0 + cB];
        pb1 = *(const float4*)&Bp[(size_t)(k0 + rB + 8) * N + col0 + cB];
    };
    ldg(0);
    for (int t = 0; t < T; ++t) {
        __syncthreads();
        // A transpose-store (k-major), convert to tf32
        As[colA + 0][rowA] = cvt_tf32(pa0.x);
        As[colA + 1][rowA] = cvt_tf32(pa0.y);
        As[colA + 2][rowA] = cvt_tf32(pa0.z);
        As[colA + 3][rowA] = cvt_tf32(pa0.w);
        As[colA + 4][rowA] = cvt_tf32(pa1.x);
        As[colA + 5][rowA] = cvt_tf32(pa1.y);
        As[colA + 6][rowA] = cvt_tf32(pa1.z);
        As[colA + 7][rowA] = cvt_tf32(pa1.w);
        Bs[rB][cB + 0] = cvt_tf32(pb0.x);
        Bs[rB][cB + 1] = cvt_tf32(pb0.y);
        Bs[rB][cB + 2] = cvt_tf32(pb0.z);
        Bs[rB][cB + 3] = cvt_tf32(pb0.w);
        Bs[rB + 8][cB + 0] = cvt_tf32(pb1.x);
        Bs[rB + 8][cB + 1] = cvt_tf32(pb1.y);
        Bs[rB + 8][cB + 2] = cvt_tf32(pb1.z);
        Bs[rB + 8][cB + 3] = cvt_tf32(pb1.w);
        __syncthreads();
        if (t + 1 < T) ldg(t + 1);
        #pragma unroll
        for (int ks = 0; ks < 16; ks += 8) {
            uint32_t af[4][4], bf[4][2];
            #pragma unroll
            for (int mt = 0; mt < 4; ++mt) {
                int m = wm + mt * 16 + grp;
                af[mt][0] = As[ks + tig][m];
                af[mt][1] = As[ks + tig][m + 8];
                af[mt][2] = As[ks + tig + 4][m];
                af[mt][3] = As[ks + tig + 4][m + 8];
            }
            #pragma unroll
            for (int nt = 0; nt < 4; ++nt) {
                int n = wn + nt * 8 + grp;
                bf[nt][0] = Bs[ks + tig][n];
                bf[nt][1] = Bs[ks + tig + 4][n];
            }
            #pragma unroll
            for (int mt = 0; mt < 4; ++mt)
                #pragma unroll
                for (int nt = 0; nt < 4; ++nt)
                    mma_tf32(c[mt][nt], af[mt][0], af[mt][1], af[mt][2], af[mt][3],
                             bf[nt][0], bf[nt][1]);
        }
    }
    // epilogue
    #pragma unroll
    for (int mt = 0; mt < 4; ++mt) {
        #pragma unroll
        for (int h = 0; h < 2; ++h) {
            int rl = wm + mt * 16 + grp + h * 8;
            long orow;
            if (GATHER) {
                int tk = toks[rl];
                if (tk < 0) continue;
                orow = tk;
            } else {
                orow = row0 + rl;
            }
            #pragma unroll
            for (int nt = 0; nt < 4; ++nt) {
                int cg = col0 + wn + nt * 8 + tig * 2;
                float v0 = c[mt][nt][h * 2 + 0];
                float v1 = c[mt][nt][h * 2 + 1];
                if (bias) { v0 += bias[cg]; v1 += bias[cg + 1]; }
                if (RES)  { v0 += res[orow * ldc + cg]; v1 += res[orow * ldc + cg + 1]; }
                *(float2*)&C[orow * ldc + cg] = make_float2(v0, v1);
            }
        }
    }
}

// ---------------- rmsnorm (float4 vectorized) ----------------
__global__ void rmsnorm_kernel(const float* __restrict__ x, const float* __restrict__ w,
                               float* __restrict__ y)
{
    int n = blockIdx.x;
    const float4* xr = (const float4*)(x + (size_t)n * Dk);
    const float4* wr = (const float4*)w;
    float4*       yr = (float4*)(y + (size_t)n * Dk);
    float s = 0.f;
    float4 v = xr[threadIdx.x];
    s = v.x * v.x + v.y * v.y + v.z * v.z + v.w * v.w;
    __shared__ float red[8];
    int lane = threadIdx.x & 31, wid = threadIdx.x >> 5;
    #pragma unroll
    for (int o = 16; o; o >>= 1) s += __shfl_xor_sync(0xffffffffu, s, o);
    if (lane == 0) red[wid] = s;
    __syncthreads();
    if (wid == 0) {
        float t = (lane < 8) ? red[lane] : 0.f;
        #pragma unroll
        for (int o = 4; o; o >>= 1) t += __shfl_xor_sync(0xffffffffu, t, o);
        if (lane == 0) red[0] = rsqrtf(t / Dk + EPS);
    }
    __syncthreads();
    float rms = red[0];
    float4 wv = wr[threadIdx.x];
    float4 out;
    out.x = v.x * rms * wv.x;
    out.y = v.y * rms * wv.y;
    out.z = v.z * rms * wv.z;
    out.w = v.w * rms * wv.w;
    yr[threadIdx.x] = out;
}

// ---------------- small 64x64 SIMT GEMM (ctrl_in only) ----------------
template<int ACT, bool DUAL>
__global__ void gemm64_kernel(const float* __restrict__ A, const float* __restrict__ B,
                              const float* __restrict__ A2, const float* __restrict__ B2,
                              const float* __restrict__ bias, float* __restrict__ C,
                              int M, int N, int K)
{
    __shared__ float As[64][16];
    __shared__ float Bs[16][64];
    int tid = threadIdx.x;
    int tx = tid & 15, ty = tid >> 4;
    int row0 = blockIdx.y * 64, col0 = blockIdx.x * 64;
    float acc[4][4] = {};

    int npass = DUAL ? 2 : 1;
    for (int pass = 0; pass < npass; ++pass) {
        const float* Ap = pass ? A2 : A;
        const float* Bp = pass ? B2 : B;
        for (int k0 = 0; k0 < K; k0 += 16) {
            #pragma unroll
            for (int i = tid; i < 64 * 16; i += 256) {
                int r = i >> 4, c = i & 15;
                As[r][c] = Ap[(size_t)(row0 + r) * K + k0 + c];
            }
            #pragma unroll
            for (int i = tid; i < 16 * 64; i += 256) {
                int r = i >> 6, c = i & 63;
                Bs[r][c] = Bp[(size_t)(k0 + r) * N + col0 + c];
            }
            __syncthreads();
            #pragma unroll
            for (int kk = 0; kk < 16; ++kk) {
                float a[4], b[4];
                #pragma unroll
                for (int i = 0; i < 4; i++) a[i] = As[ty * 4 + i][kk];
                #pragma unroll
                for (int j = 0; j < 4; j++) b[j] = Bs[kk][tx * 4 + j];
                #pragma unroll
                for (int i = 0; i < 4; i++)
                    #pragma unroll
                    for (int j = 0; j < 4; j++)
                        acc[i][j] += a[i] * b[j];
            }
            __syncthreads();
        }
    }
    #pragma unroll
    for (int i = 0; i < 4; i++) {
        int r = row0 + ty * 4 + i;
        #pragma unroll
        for (int j = 0; j < 4; j++) {
            int c = col0 + tx * 4 + j;
            float v = acc[i][j];
            if (bias) v += bias[c];
            if (ACT == 1) v = v / (1.f + expf(-v));   // silu
            C[(size_t)r * N + c] = v;
        }
    }
}

// ---------------- q/k rmsnorm + rope ----------------
__global__ void qknorm_rope_kernel(float* __restrict__ q, float* __restrict__ k,
                                   const int* __restrict__ positions,
                                   const float* __restrict__ qw, const float* __restrict__ kw)
{
    int n = blockIdx.x;
    int hh = blockIdx.y;   // 0..H+KV-1
    float* x; const float* w;
    if (hh < Hh) { x = q + ((size_t)n * Hh + hh) * DHd; w = qw; }
    else         { x = k + ((size_t)n * KVh + (hh - Hh)) * DHd; w = kw; }
    int lane = threadIdx.x;  // 0..31
    float x1 = x[lane], x2 = x[lane + 32];
    float s = x1 * x1 + x2 * x2;
    #pragma unroll
    for (int o = 16; o; o >>= 1) s += __shfl_xor_sync(0xffffffffu, s, o);
    float rms = rsqrtf(s / 64.f + EPS);
    float v1 = x1 * rms * w[lane];
    float v2 = x2 * rms * w[lane + 32];
    float inv = (float)exp(-(2.0 * (double)lane / 64.0) * log(10000.0));
    float ang = (float)positions[n] * inv;
    float c = cosf(ang), sn = sinf(ang);
    x[lane]      = v1 * c - v2 * sn;
    x[lane + 32] = v2 * c + v1 * sn;
}

// ---------------- flash-style attention (fp32, static smem) ----------------
__global__ void attn_kernel(const float* __restrict__ q, const float* __restrict__ k,
                            const float* __restrict__ v, float* __restrict__ o)
{
    __shared__ float Qs[32][64];
    __shared__ float KVs[64][65];
    __shared__ float Ss[32][65];
    __shared__ float mrow[32], lrow[32], crow[32];

    int h = blockIdx.y;
    int kvh = h >> 2;          // H/KV = 4
    int q0 = blockIdx.x * 32;
    int tid = threadIdx.x;
    int tx = tid & 63, ty = tid >> 6;

    for (int r = ty; r < 32; r += 4)
        Qs[r][tx] = q[((size_t)(q0 + r) * Hh + h) * DHd + tx];
    if (tid < 32) { mrow[tid] = -1e30f; lrow[tid] = 0.f; }
    float acc[8];
    #pragma unroll
    for (int i = 0; i < 8; i++) acc[i] = 0.f;
    __syncthreads();

    for (int kt = 0; kt < Nn / 64; ++kt) {
        int kb = kt * 64;
        for (int r = ty; r < 64; r += 4)
            KVs[r][tx] = k[((size_t)(kb + r) * KVh + kvh) * DHd + tx];
        __syncthreads();
        #pragma unroll
        for (int i = 0; i < 8; ++i) {
            int r = ty + i * 4;
            float s = 0.f;
            #pragma unroll
            for (int d = 0; d < 64; ++d) s += Qs[r][d] * KVs[tx][d];
            Ss[r][tx] = s * 0.125f;
        }
        __syncthreads();
        if (tid < 32) {
            int r = tid;
            float mx = -1e30f;
            #pragma unroll 8
            for (int c = 0; c < 64; ++c) mx = fmaxf(mx, Ss[r][c]);
            float mnew = fmaxf(mrow[r], mx);
            float corr = expf(mrow[r] - mnew);
            float lsum = 0.f;
            #pragma unroll 8
            for (int c = 0; c < 64; ++c) {
                float p = expf(Ss[r][c] - mnew);
                Ss[r][c] = p; lsum += p;
            }
            lrow[r] = lrow[r] * corr + lsum;
            mrow[r] = mnew;
            crow[r] = corr;
        }
        __syncthreads();
        for (int r = ty; r < 64; r += 4)
            KVs[r][tx] = v[((size_t)(kb + r) * KVh + kvh) * DHd + tx];
        __syncthreads();
        #pragma unroll
        for (int i = 0; i < 8; ++i) {
            int r = ty + i * 4;
            float s = 0.f;
            #pragma unroll
            for (int c = 0; c < 64; ++c) s += Ss[r][c] * KVs[c][tx];
            acc[i] = acc[i] * crow[r] + s;
        }
        __syncthreads();
    }
    #pragma unroll
    for (int i = 0; i < 8; ++i) {
        int r = ty + i * 4;
        o[((size_t)(q0 + r) * Hh + h) * DHd + tx] = acc[i] / lrow[r];
    }
}

// ---------------- dynamics (elementwise, float4) ----------------
__global__ void dynamics_kernel(const float4* __restrict__ hidden_in,
                                const float4* __restrict__ velocity,
                                const float4* __restrict__ oproj,
                                const float4* __restrict__ mu,
                                const float* __restrict__ co,
                                float4* __restrict__ v_out,
                                float4* __restrict__ hidden2)
{
    int idx = blockIdx.x * blockDim.x + threadIdx.x;
    if (idx >= Nn * Dk / 4) return;
    int n = idx / (Dk / 4), c4 = idx - n * (Dk / 4);
    const float4* cr = (const float4*)(co + (size_t)n * 3 * Dk);
    float4 a_raw  = cr[c4];
    float4 b_raw  = cr[Dk / 4 + c4];
    float4 gt_raw = cr[2 * Dk / 4 + c4];
    float4 ov  = oproj[idx];
    float4 muv = mu[idx];
    float4 vel = velocity[idx];
    float4 hin = hidden_in[idx];
    float4 vn, h2;
    #pragma unroll
    for (int j = 0; j < 4; ++j) {
        float ar = (&a_raw.x)[j], br = (&b_raw.x)[j], gr = (&gt_raw.x)[j];
        float alpha = 1.f / (1.f + expf(-ar));
        float sp = (br > 20.f) ? br : log1pf(expf(br));
        float beta = fminf(sp, 2.f);
        float gate = 1.f / (1.f + expf(-gr));
        float o = (&ov.x)[j];
        float err = o - (&muv.x)[j];
        float vv = alpha * (&vel.x)[j] - beta * err;
        vv = fminf(fmaxf(vv, -10.f), 10.f);
        (&vn.x)[j] = vv;
        (&h2.x)[j] = (&hin.x)[j] + o + DT * gate * vv;
    }
    v_out[idx] = vn;
    hidden2[idx] = h2;
}

// ---------------- router ----------------
__global__ void reset_counts_kernel()
{
    if (threadIdx.x < Ee) g_counts[threadIdx.x] = 0;
}

__global__ void router_kernel(const float* __restrict__ mu, const float* __restrict__ W,
                              const int* __restrict__ token_ids)
{
    int gwarp = (blockIdx.x * blockDim.x + threadIdx.x) >> 5;
    int lane = threadIdx.x & 31;
    if (gwarp >= Nn) return;
    float acc[Ee] = {};
    const float* m = mu + (size_t)gwarp * Dk;
    for (int d = lane; d < Dk; d += 32) {
        float mv = m[d];
        #pragma unroll
        for (int e = 0; e < Ee; ++e) acc[e] += mv * W[d * Ee + e];
    }
    #pragma unroll
    for (int o = 16; o; o >>= 1)
        #pragma unroll
        for (int e = 0; e < Ee; ++e) acc[e] += __shfl_xor_sync(0xffffffffu, acc[e], o);
    if (lane == 0) {
        int base = token_ids[gwarp] % Ee;
        int best = 0; float bv = -1e30f;
        #pragma unroll
        for (int e = 0; e < Ee; ++e) {
            float vv = acc[e] + (e == base ? BASE_SCALE : 0.f);
            if (vv > bv) { bv = vv; best = e; }
        }
        int pos = atomicAdd(&g_counts[best], 1);
        g_list[best * Nn + pos] = gwarp;
    }
}

// ---------------- silu(g)*u elementwise ----------------
__global__ void silumul_kernel(const float4* __restrict__ G, const float4* __restrict__ U,
                               float4* __restrict__ Mid)
{
    int idx = blockIdx.x * blockDim.x + threadIdx.x;
    if (idx >= Nn * Ff / 4) return;
    float4 g = G[idx], u = U[idx], o;
    #pragma unroll
    for (int j = 0; j < 4; ++j) {
        float gv = (&g.x)[j];
        float sg = gv / (1.f + expf(-gv));
        (&o.x)[j] = sg * (&u.x)[j];
    }
    Mid[idx] = o;
}

// ---------------- launch ----------------
static float* sym(const void* s)
{
    void* p = nullptr;
    cudaGetSymbolAddress(&p, s);
    return (float*)p;
}

extern "C" void kernel_launch(void* const* d_in, const int* in_sizes, int n_in,
                              void* d_out, int out_size)
{
    const float* hidden        = (const float*)d_in[0];
    const int*   positions     = (const int*)  d_in[1];
    const float* velocity      = (const float*)d_in[2];
    const int*   token_ids     = (const int*)  d_in[3];
    const float* mu_prev       = (const float*)d_in[4];
    const float* ln1_w         = (const float*)d_in[5];
    const float* ln2_w         = (const float*)d_in[6];
    const float* wq            = (const float*)d_in[7];
    const float* wk            = (const float*)d_in[8];
    const float* wv            = (const float*)d_in[9];
    const float* wo            = (const float*)d_in[10];
    const float* w_mu_q        = (const float*)d_in[11];
    const float* w_mu_k        = (const float*)d_in[12];
    const float* w_mu_v        = (const float*)d_in[13];
    const float* qnorm_w       = (const float*)d_in[14];
    const float* knorm_w       = (const float*)d_in[15];
    const float* dyn_mu        = (const float*)d_in[16];
    const float* dyn_mu_proj_w = (const float*)d_in[17];
    const float* ctrl_in_w     = (const float*)d_in[18];
    const float* ctrl_in_b     = (const float*)d_in[19];
    const float* ctrl_out_w    = (const float*)d_in[20];
    const float* ctrl_out_b    = (const float*)d_in[21];
    const float* mu_router_w   = (const float*)d_in[22];
    const float* w_gate        = (const float*)d_in[23];
    const float* w_up          = (const float*)d_in[24];
    const float* w_down        = (const float*)d_in[25];

    float* out_hidden = (float*)d_out;
    float* out_v      = out_hidden + (size_t)Nn * Dk;
    float* out_mu     = out_v + (size_t)Nn * Dk;

    float* h1   = sym(g_h1);
    float* qb   = sym(g_q);
    float* kb   = sym(g_k);
    float* vb   = sym(g_v);
    float* ob   = sym(g_o);
    float* op   = sym(g_oproj);
    float* ctrl = sym(g_ctrl);
    float* co   = sym(g_co);
    float* h2   = sym(g_hidden2);
    float* x2   = sym(g_x2);
    float* midg = sym(g_midg);
    float* midu = sym(g_midu);
    float* mid  = sym(g_mid);

    // 1) rmsnorm1
    rmsnorm_kernel<<<Nn, 256>>>(hidden, ln1_w, h1);

    // 2) QKV = h1@W + mu_prev@W_mu  (tf32 mma, dual pass)
    mma_gemm_kernel<false, true, false><<<dim3(Hh * DHd / 128, Nn / 128), 256>>>(
        h1, wq, mu_prev, w_mu_q, nullptr, nullptr, qb, Hh * DHd, Dk, Dk, Hh * DHd);
    mma_gemm_kernel<false, true, false><<<dim3(KVh * DHd / 128, Nn / 128), 256>>>(
        h1, wk, mu_prev, w_mu_k, nullptr, nullptr, kb, KVh * DHd, Dk, Dk, KVh * DHd);
    mma_gemm_kernel<false, true, false><<<dim3(KVh * DHd / 128, Nn / 128), 256>>>(
        h1, wv, mu_prev, w_mu_v, nullptr, nullptr, vb, KVh * DHd, Dk, Dk, KVh * DHd);

    // 3) q/k norm + rope (in place)
    qknorm_rope_kernel<<<dim3(Nn, Hh + KVh), 32>>>(qb, kb, positions, qnorm_w, knorm_w);

    // 4) attention (fp32)
    attn_kernel<<<dim3(Nn / 32, Hh), 256>>>(qb, kb, vb, ob);

    // 5) o-proj (tf32)
    mma_gemm_kernel<false, false, false><<<dim3(Dk / 128, Nn / 128), 256>>>(
        ob, wo, nullptr, nullptr, nullptr, nullptr, op, Dk, Hh * DHd, Hh * DHd, Dk);

    // 6) mu_cur = dyn_mu + oproj @ dyn_mu_proj_w (tf32, direct to output)
    mma_gemm_kernel<false, false, false><<<dim3(Dk / 128, Nn / 128), 256>>>(
        op, dyn_mu_proj_w, nullptr, nullptr, dyn_mu, nullptr, out_mu, Dk, Dk, Dk, Dk);

    // 7) ctrl = silu([o, velocity] @ ctrl_in_w + b)   (N=64 -> SIMT 64-wide)
    gemm64_kernel<1, true><<<dim3(CHc / 64, Nn / 64), 256>>>(op, ctrl_in_w, velocity,
        ctrl_in_w + (size_t)Dk * CHc, ctrl_in_b, ctrl, Nn, CHc, Dk);

    // 8) co = ctrl @ ctrl_out_w + b  (tf32, K=64)
    mma_gemm_kernel<false, false, false><<<dim3(3 * Dk / 128, Nn / 128), 256>>>(
        ctrl, ctrl_out_w, nullptr, nullptr, ctrl_out_b, nullptr, co, 3 * Dk, CHc, CHc, 3 * Dk);

    // 9) dynamics: v_next (output), hidden2
    dynamics_kernel<<<(Nn * Dk / 4 + 255) / 256, 256>>>((const float4*)hidden, (const float4*)velocity,
                                                        (const float4*)op, (const float4*)out_mu, co,
                                                        (float4*)out_v, (float4*)h2);

    // 10) rmsnorm2
    rmsnorm_kernel<<<Nn, 256>>>(h2, ln2_w, x2);

    // 11) router
    reset_counts_kernel<<<1, 32>>>();
    router_kernel<<<(Nn * 32 + 255) / 256, 256>>>(out_mu, mu_router_w, token_ids);

    // 12) MoE gate & up (tf32, gathered)
    mma_gemm_kernel<true, false, false><<<dim3(Ff / 128, Nn / 128, Ee), 256>>>(
        x2, w_gate, nullptr, nullptr, nullptr, nullptr, midg, Ff, Dk, Dk, Ff);
    mma_gemm_kernel<true, false, false><<<dim3(Ff / 128, Nn / 128, Ee), 256>>>(
        x2, w_up, nullptr, nullptr, nullptr, nullptr, midu, Ff, Dk, Dk, Ff);

    // 12b) mid = silu(g) * u
    silumul_kernel<<<(Nn * Ff / 4 + 255) / 256, 256>>>((const float4*)midg, (const float4*)midu,
                                                       (float4*)mid);

    // 13) MoE down + residual -> final hidden (tf32, gathered)
    mma_gemm_kernel<true, false, true><<<dim3(Dk / 128, Nn / 128, Ee), 256>>>(
        mid, w_down, nullptr, nullptr, nullptr, h2, out_hidden, Dk, Ff, Ff, Dk);
}

// round 9
// speedup vs baseline: 2.5561x; 1.2510x over previous
#include <cuda_runtime.h>
#include <cuda_bf16.h>
#include <cstdint>
#include <cmath>

// Problem constants
constexpr int Nn  = 2048;   // tokens
constexpr int Dk  = 1024;   // model dim
constexpr int Hh  = 16;     // q heads
constexpr int KVh = 4;      // kv heads
constexpr int DHd = 64;     // head dim
constexpr int Ee  = 8;      // experts
constexpr int Ff  = 2048;   // ffn dim
constexpr int CHc = 64;     // ctrl hidden
constexpr float EPS = 1e-6f;
constexpr float DT  = 0.1f;
constexpr float BASE_SCALE = 10.0f;

// ---------------- device scratch (static, allowed) ----------------
__device__ float g_h1[Nn * Dk];
__device__ float g_q[Nn * Hh * DHd];
__device__ float g_k[Nn * KVh * DHd];
__device__ float g_v[Nn * KVh * DHd];
__device__ float g_o[Nn * Hh * DHd];
__device__ float g_oproj[Nn * Dk];
__device__ float g_ctrl[Nn * CHc];
__device__ float g_co[Nn * 3 * Dk];
__device__ float g_hidden2[Nn * Dk];
__device__ float g_x2[Nn * Dk];
__device__ float g_midg[Nn * Ff];
__device__ float g_midu[Nn * Ff];
__device__ float g_mid[Nn * Ff];
__device__ int   g_counts[Ee];
__device__ int   g_list[Ee * Nn];

// ---------------- tf32 helpers ----------------
__device__ __forceinline__ uint32_t cvt_tf32(float x) {
    uint32_t r;
    asm("cvt.rna.tf32.f32 %0, %1;" : "=r"(r) : "f"(x));
    return r;
}

__device__ __forceinline__ void mma_tf32(float c[4],
    uint32_t a0, uint32_t a1, uint32_t a2, uint32_t a3,
    uint32_t b0, uint32_t b1)
{
    asm volatile("mma.sync.aligned.m16n8k8.row.col.f32.tf32.tf32.f32 "
        "{%0,%1,%2,%3}, {%4,%5,%6,%7}, {%8,%9}, {%0,%1,%2,%3};"
        : "+f"(c[0]), "+f"(c[1]), "+f"(c[2]), "+f"(c[3])
        : "r"(a0), "r"(a1), "r"(a2), "r"(a3), "r"(b0), "r"(b1));
}

// fast exp via 2^f polynomial (degree 6 Taylor of 2^f on [0,1), rel err ~8e-6)
__device__ __forceinline__ float fexp(float x) {
    float t = x * 1.442695040888963f;
    t = fmaxf(t, -126.0f);
    int i = __float2int_rd(t);
    float f = t - (float)i;
    float p =         1.540353039e-4f;
    p = fmaf(p, f, 1.333355815e-3f);
    p = fmaf(p, f, 9.618129108e-3f);
    p = fmaf(p, f, 5.550410866e-2f);
    p = fmaf(p, f, 2.402265070e-1f);
    p = fmaf(p, f, 6.931471806e-1f);
    p = fmaf(p, f, 1.0f);
    return p * __int_as_float((i + 127) << 23);
}

// ============================================================================
// Unified tf32 tensor-core GEMM: C[M,N] = act(A@B (+A2@B2) (+bias)) (+res)
// BM=128, BN=128 or 64, BK=16, 256 threads (8 warps), double-buffered smem.
// BN=128: warp tile 64x32 (MT=4). BN=64: warp tile 32x32 (MT=2).
// GATHER: A rows via g_list/g_counts[blockIdx.z], B += e*K*N, C scatter.
// ============================================================================
template<bool GATHER, bool DUAL, bool RES, int BN, int ACT>
__global__ __launch_bounds__(256, 1)
void mma_gemm_kernel(const float* __restrict__ A, const float* __restrict__ Bw,
                     const float* __restrict__ A2, const float* __restrict__ B2,
                     const float* __restrict__ bias, const float* __restrict__ res,
                     float* __restrict__ C, int N, int K, int lda, int ldc)
{
    constexpr int MT = (BN == 128) ? 4 : 2;
    __shared__ uint32_t As[2][16][136];
    __shared__ uint32_t Bs[2][16][BN + 8];
    __shared__ int toks[128];

    const float* B = Bw;
    int row0 = blockIdx.y * 128;
    if (GATHER) {
        int e = blockIdx.z;
        int cnt = g_counts[e];
        if (row0 >= cnt) return;
        B += (size_t)e * K * N;
        if (threadIdx.x < 128) {
            int idx = row0 + threadIdx.x;
            toks[threadIdx.x] = (idx < cnt) ? g_list[e * Nn + idx] : -1;
        }
        __syncthreads();
    }
    int col0 = blockIdx.x * BN;
    int tid  = threadIdx.x;
    int lane = tid & 31, warp = tid >> 5;
    int grp = lane >> 2, tig = lane & 3;
    int wm = (BN == 128) ? (warp >> 2) * 64 : (warp >> 1) * 32;
    int wn = (BN == 128) ? (warp & 3) * 32 : (warp & 1) * 32;

    int rowA = tid >> 1, colA = (tid & 1) << 3;    // A: 8 floats / thread
    // B loaders
    int rB128 = tid >> 5, cB128 = (lane) << 2;     // BN=128: 2x float4
    int rB64  = tid >> 4, cB64  = (tid & 15) << 2; // BN=64:  1x float4

    long aRow = GATHER ? (long)toks[rowA] : (long)(row0 + rowA);

    float c[MT][4][4];
    #pragma unroll
    for (int i = 0; i < MT; i++)
        #pragma unroll
        for (int j = 0; j < 4; j++)
            #pragma unroll
            for (int l = 0; l < 4; l++) c[i][j][l] = 0.f;

    const int TK = K / 16;
    const int T = (DUAL ? 2 : 1) * TK;
    float4 pa0, pa1, pb0, pb1;

    auto ldg = [&](int t) {
        int pass = DUAL ? (t >= TK) : 0;
        int k0 = (pass ? t - TK : t) << 4;
        const float* Ap = pass ? A2 : A;
        const float* Bp = pass ? B2 : B;
        if (!GATHER || aRow >= 0) {
            const float* ar = Ap + (size_t)aRow * lda + k0 + colA;
            pa0 = *(const float4*)ar;
            pa1 = *(const float4*)(ar + 4);
        } else {
            pa0 = make_float4(0, 0, 0, 0);
            pa1 = make_float4(0, 0, 0, 0);
        }
        if (BN == 128) {
            pb0 = *(const float4*)&Bp[(size_t)(k0 + rB128) * N + col0 + cB128];
            pb1 = *(const float4*)&Bp[(size_t)(k0 + rB128 + 8) * N + col0 + cB128];
        } else {
            pb0 = *(const float4*)&Bp[(size_t)(k0 + rB64) * N + col0 + cB64];
        }
    };
    auto sts = [&](int db) {
        As[db][colA + 0][rowA] = cvt_tf32(pa0.x);
        As[db][colA + 1][rowA] = cvt_tf32(pa0.y);
        As[db][colA + 2][rowA] = cvt_tf32(pa0.z);
        As[db][colA + 3][rowA] = cvt_tf32(pa0.w);
        As[db][colA + 4][rowA] = cvt_tf32(pa1.x);
        As[db][colA + 5][rowA] = cvt_tf32(pa1.y);
        As[db][colA + 6][rowA] = cvt_tf32(pa1.z);
        As[db][colA + 7][rowA] = cvt_tf32(pa1.w);
        if (BN == 128) {
            Bs[db][rB128][cB128 + 0] = cvt_tf32(pb0.x);
            Bs[db][rB128][cB128 + 1] = cvt_tf32(pb0.y);
            Bs[db][rB128][cB128 + 2] = cvt_tf32(pb0.z);
            Bs[db][rB128][cB128 + 3] = cvt_tf32(pb0.w);
            Bs[db][rB128 + 8][cB128 + 0] = cvt_tf32(pb1.x);
            Bs[db][rB128 + 8][cB128 + 1] = cvt_tf32(pb1.y);
            Bs[db][rB128 + 8][cB128 + 2] = cvt_tf32(pb1.z);
            Bs[db][rB128 + 8][cB128 + 3] = cvt_tf32(pb1.w);
        } else {
            Bs[db][rB64][cB64 + 0] = cvt_tf32(pb0.x);
            Bs[db][rB64][cB64 + 1] = cvt_tf32(pb0.y);
            Bs[db][rB64][cB64 + 2] = cvt_tf32(pb0.z);
            Bs[db][rB64][cB64 + 3] = cvt_tf32(pb0.w);
        }
    };
    auto compute = [&](int db) {
        #pragma unroll
        for (int ks = 0; ks < 16; ks += 8) {
            uint32_t af[MT][4], bf[4][2];
            #pragma unroll
            for (int mt = 0; mt < MT; ++mt) {
                int m = wm + mt * 16 + grp;
                af[mt][0] = As[db][ks + tig][m];
                af[mt][1] = As[db][ks + tig][m + 8];
                af[mt][2] = As[db][ks + tig + 4][m];
                af[mt][3] = As[db][ks + tig + 4][m + 8];
            }
            #pragma unroll
            for (int nt = 0; nt < 4; ++nt) {
                int n = wn + nt * 8 + grp;
                bf[nt][0] = Bs[db][ks + tig][n];
                bf[nt][1] = Bs[db][ks + tig + 4][n];
            }
            #pragma unroll
            for (int mt = 0; mt < MT; ++mt)
                #pragma unroll
                for (int nt = 0; nt < 4; ++nt)
                    mma_tf32(c[mt][nt], af[mt][0], af[mt][1], af[mt][2], af[mt][3],
                             bf[nt][0], bf[nt][1]);
        }
    };

    // pipeline: ldg(0) -> sts(buf0) -> ldg(1) -> sync; loop with one sync/tile
    ldg(0);
    sts(0);
    if (T > 1) ldg(1);
    __syncthreads();
    for (int t = 0; t < T; ++t) {
        if (t + 1 < T) sts((t + 1) & 1);
        if (t + 2 < T) ldg(t + 2);
        compute(t & 1);
        __syncthreads();
    }

    // epilogue
    #pragma unroll
    for (int mt = 0; mt < MT; ++mt) {
        #pragma unroll
        for (int h = 0; h < 2; ++h) {
            int rl = wm + mt * 16 + grp + h * 8;
            long orow;
            if (GATHER) {
                int tk = toks[rl];
                if (tk < 0) continue;
                orow = tk;
            } else {
                orow = row0 + rl;
            }
            #pragma unroll
            for (int nt = 0; nt < 4; ++nt) {
                int cg = col0 + wn + nt * 8 + tig * 2;
                float v0 = c[mt][nt][h * 2 + 0];
                float v1 = c[mt][nt][h * 2 + 1];
                if (bias) { v0 += bias[cg]; v1 += bias[cg + 1]; }
                if (ACT == 1) {
                    v0 = v0 / (1.f + expf(-v0));
                    v1 = v1 / (1.f + expf(-v1));
                }
                if (RES)  { v0 += res[orow * ldc + cg]; v1 += res[orow * ldc + cg + 1]; }
                *(float2*)&C[orow * ldc + cg] = make_float2(v0, v1);
            }
        }
    }
}

// ---------------- rmsnorm (float4 vectorized) ----------------
__global__ void rmsnorm_kernel(const float* __restrict__ x, const float* __restrict__ w,
                               float* __restrict__ y)
{
    int n = blockIdx.x;
    const float4* xr = (const float4*)(x + (size_t)n * Dk);
    const float4* wr = (const float4*)w;
    float4*       yr = (float4*)(y + (size_t)n * Dk);
    float s = 0.f;
    float4 v = xr[threadIdx.x];
    s = v.x * v.x + v.y * v.y + v.z * v.z + v.w * v.w;
    __shared__ float red[8];
    int lane = threadIdx.x & 31, wid = threadIdx.x >> 5;
    #pragma unroll
    for (int o = 16; o; o >>= 1) s += __shfl_xor_sync(0xffffffffu, s, o);
    if (lane == 0) red[wid] = s;
    __syncthreads();
    if (wid == 0) {
        float t = (lane < 8) ? red[lane] : 0.f;
        #pragma unroll
        for (int o = 4; o; o >>= 1) t += __shfl_xor_sync(0xffffffffu, t, o);
        if (lane == 0) red[0] = rsqrtf(t / Dk + EPS);
    }
    __syncthreads();
    float rms = red[0];
    float4 wv = wr[threadIdx.x];
    float4 out;
    out.x = v.x * rms * wv.x;
    out.y = v.y * rms * wv.y;
    out.z = v.z * rms * wv.z;
    out.w = v.w * rms * wv.w;
    yr[threadIdx.x] = out;
}

// ---------------- q/k rmsnorm + rope ----------------
__global__ void qknorm_rope_kernel(float* __restrict__ q, float* __restrict__ k,
                                   const int* __restrict__ positions,
                                   const float* __restrict__ qw, const float* __restrict__ kw)
{
    int n = blockIdx.x;
    int hh = blockIdx.y;   // 0..H+KV-1
    float* x; const float* w;
    if (hh < Hh) { x = q + ((size_t)n * Hh + hh) * DHd; w = qw; }
    else         { x = k + ((size_t)n * KVh + (hh - Hh)) * DHd; w = kw; }
    int lane = threadIdx.x;  // 0..31
    float x1 = x[lane], x2 = x[lane + 32];
    float s = x1 * x1 + x2 * x2;
    #pragma unroll
    for (int o = 16; o; o >>= 1) s += __shfl_xor_sync(0xffffffffu, s, o);
    float rms = rsqrtf(s / 64.f + EPS);
    float v1 = x1 * rms * w[lane];
    float v2 = x2 * rms * w[lane + 32];
    float inv = (float)exp(-(2.0 * (double)lane / 64.0) * log(10000.0));
    float ang = (float)positions[n] * inv;
    float c = cosf(ang), sn = sinf(ang);
    x[lane]      = v1 * c - v2 * sn;
    x[lane + 32] = v2 * c + v1 * sn;
}

// ---------------- flash-style attention (fp32, parallel softmax, fast exp) --
__global__ void attn_kernel(const float* __restrict__ q, const float* __restrict__ k,
                            const float* __restrict__ v, float* __restrict__ o)
{
    __shared__ float Qs[32][64];
    __shared__ float KVs[64][65];
    __shared__ float Ss[32][65];
    __shared__ float mrow[32], lrow[32], crow[32];

    int h = blockIdx.y;
    int kvh = h >> 2;          // H/KV = 4
    int q0 = blockIdx.x * 32;
    int tid = threadIdx.x;
    int tx = tid & 63, ty = tid >> 6;
    int sr = tid >> 3;         // softmax row 0..31
    int t8 = tid & 7;          // softmax lane within row

    for (int r = ty; r < 32; r += 4)
        Qs[r][tx] = q[((size_t)(q0 + r) * Hh + h) * DHd + tx];
    if (tid < 32) { mrow[tid] = -1e30f; lrow[tid] = 0.f; }
    float acc[8];
    #pragma unroll
    for (int i = 0; i < 8; i++) acc[i] = 0.f;
    __syncthreads();

    for (int kt = 0; kt < Nn / 64; ++kt) {
        int kb = kt * 64;
        for (int r = ty; r < 64; r += 4)
            KVs[r][tx] = k[((size_t)(kb + r) * KVh + kvh) * DHd + tx];
        __syncthreads();
        #pragma unroll
        for (int i = 0; i < 8; ++i) {
            int r = ty + i * 4;
            float s = 0.f;
            #pragma unroll
            for (int d = 0; d < 64; ++d) s += Qs[r][d] * KVs[tx][d];
            Ss[r][tx] = s * 0.125f;
        }
        __syncthreads();
        // parallel online softmax: 8 lanes per row, all 256 threads active
        {
            float mx = -1e30f;
            #pragma unroll
            for (int j = 0; j < 8; ++j) mx = fmaxf(mx, Ss[sr][t8 * 8 + j]);
            #pragma unroll
            for (int off = 1; off < 8; off <<= 1)
                mx = fmaxf(mx, __shfl_xor_sync(0xffffffffu, mx, off));
            float mold = mrow[sr];
            float mnew = fmaxf(mold, mx);
            float corr = fexp(mold - mnew);
            float lsum = 0.f;
            #pragma unroll
            for (int j = 0; j < 8; ++j) {
                float p = fexp(Ss[sr][t8 * 8 + j] - mnew);
                Ss[sr][t8 * 8 + j] = p;
                lsum += p;
            }
            #pragma unroll
            for (int off = 1; off < 8; off <<= 1)
                lsum += __shfl_xor_sync(0xffffffffu, lsum, off);
            __syncwarp();
            if (t8 == 0) {
                lrow[sr] = lrow[sr] * corr + lsum;
                mrow[sr] = mnew;
                crow[sr] = corr;
            }
        }
        __syncthreads();
        for (int r = ty; r < 64; r += 4)
            KVs[r][tx] = v[((size_t)(kb + r) * KVh + kvh) * DHd + tx];
        __syncthreads();
        #pragma unroll
        for (int i = 0; i < 8; ++i) {
            int r = ty + i * 4;
            float s = 0.f;
            #pragma unroll
            for (int c = 0; c < 64; ++c) s += Ss[r][c] * KVs[c][tx];
            acc[i] = acc[i] * crow[r] + s;
        }
        __syncthreads();
    }
    #pragma unroll
    for (int i = 0; i < 8; ++i) {
        int r = ty + i * 4;
        o[((size_t)(q0 + r) * Hh + h) * DHd + tx] = acc[i] / lrow[r];
    }
}

// ---------------- dynamics (elementwise, float4) ----------------
__global__ void dynamics_kernel(const float4* __restrict__ hidden_in,
                                const float4* __restrict__ velocity,
                                const float4* __restrict__ oproj,
                                const float4* __restrict__ mu,
                                const float* __restrict__ co,
                                float4* __restrict__ v_out,
                                float4* __restrict__ hidden2)
{
    int idx = blockIdx.x * blockDim.x + threadIdx.x;
    if (idx >= Nn * Dk / 4) return;
    int n = idx / (Dk / 4), c4 = idx - n * (Dk / 4);
    const float4* cr = (const float4*)(co + (size_t)n * 3 * Dk);
    float4 a_raw  = cr[c4];
    float4 b_raw  = cr[Dk / 4 + c4];
    float4 gt_raw = cr[2 * Dk / 4 + c4];
    float4 ov  = oproj[idx];
    float4 muv = mu[idx];
    float4 vel = velocity[idx];
    float4 hin = hidden_in[idx];
    float4 vn, h2;
    #pragma unroll
    for (int j = 0; j < 4; ++j) {
        float ar = (&a_raw.x)[j], br = (&b_raw.x)[j], gr = (&gt_raw.x)[j];
        float alpha = 1.f / (1.f + expf(-ar));
        float sp = (br > 20.f) ? br : log1pf(expf(br));
        float beta = fminf(sp, 2.f);
        float gate = 1.f / (1.f + expf(-gr));
        float o = (&ov.x)[j];
        float err = o - (&muv.x)[j];
        float vv = alpha * (&vel.x)[j] - beta * err;
        vv = fminf(fmaxf(vv, -10.f), 10.f);
        (&vn.x)[j] = vv;
        (&h2.x)[j] = (&hin.x)[j] + o + DT * gate * vv;
    }
    v_out[idx] = vn;
    hidden2[idx] = h2;
}

// ---------------- router ----------------
__global__ void reset_counts_kernel()
{
    if (threadIdx.x < Ee) g_counts[threadIdx.x] = 0;
}

__global__ void router_kernel(const float* __restrict__ mu, const float* __restrict__ W,
                              const int* __restrict__ token_ids)
{
    int gwarp = (blockIdx.x * blockDim.x + threadIdx.x) >> 5;
    int lane = threadIdx.x & 31;
    if (gwarp >= Nn) return;
    float acc[Ee] = {};
    const float* m = mu + (size_t)gwarp * Dk;
    for (int d = lane; d < Dk; d += 32) {
        float mv = m[d];
        #pragma unroll
        for (int e = 0; e < Ee; ++e) acc[e] += mv * W[d * Ee + e];
    }
    #pragma unroll
    for (int o = 16; o; o >>= 1)
        #pragma unroll
        for (int e = 0; e < Ee; ++e) acc[e] += __shfl_xor_sync(0xffffffffu, acc[e], o);
    if (lane == 0) {
        int base = token_ids[gwarp] % Ee;
        int best = 0; float bv = -1e30f;
        #pragma unroll
        for (int e = 0; e < Ee; ++e) {
            float vv = acc[e] + (e == base ? BASE_SCALE : 0.f);
            if (vv > bv) { bv = vv; best = e; }
        }
        int pos = atomicAdd(&g_counts[best], 1);
        g_list[best * Nn + pos] = gwarp;
    }
}

// ---------------- silu(g)*u elementwise ----------------
__global__ void silumul_kernel(const float4* __restrict__ G, const float4* __restrict__ U,
                               float4* __restrict__ Mid)
{
    int idx = blockIdx.x * blockDim.x + threadIdx.x;
    if (idx >= Nn * Ff / 4) return;
    float4 g = G[idx], u = U[idx], o;
    #pragma unroll
    for (int j = 0; j < 4; ++j) {
        float gv = (&g.x)[j];
        float sg = gv / (1.f + expf(-gv));
        (&o.x)[j] = sg * (&u.x)[j];
    }
    Mid[idx] = o;
}

// ---------------- launch ----------------
static float* sym(const void* s)
{
    void* p = nullptr;
    cudaGetSymbolAddress(&p, s);
    return (float*)p;
}

extern "C" void kernel_launch(void* const* d_in, const int* in_sizes, int n_in,
                              void* d_out, int out_size)
{
    const float* hidden        = (const float*)d_in[0];
    const int*   positions     = (const int*)  d_in[1];
    const float* velocity      = (const float*)d_in[2];
    const int*   token_ids     = (const int*)  d_in[3];
    const float* mu_prev       = (const float*)d_in[4];
    const float* ln1_w         = (const float*)d_in[5];
    const float* ln2_w         = (const float*)d_in[6];
    const float* wq            = (const float*)d_in[7];
    const float* wk            = (const float*)d_in[8];
    const float* wv            = (const float*)d_in[9];
    const float* wo            = (const float*)d_in[10];
    const float* w_mu_q        = (const float*)d_in[11];
    const float* w_mu_k        = (const float*)d_in[12];
    const float* w_mu_v        = (const float*)d_in[13];
    const float* qnorm_w       = (const float*)d_in[14];
    const float* knorm_w       = (const float*)d_in[15];
    const float* dyn_mu        = (const float*)d_in[16];
    const float* dyn_mu_proj_w = (const float*)d_in[17];
    const float* ctrl_in_w     = (const float*)d_in[18];
    const float* ctrl_in_b     = (const float*)d_in[19];
    const float* ctrl_out_w    = (const float*)d_in[20];
    const float* ctrl_out_b    = (const float*)d_in[21];
    const float* mu_router_w   = (const float*)d_in[22];
    const float* w_gate        = (const float*)d_in[23];
    const float* w_up          = (const float*)d_in[24];
    const float* w_down        = (const float*)d_in[25];

    float* out_hidden = (float*)d_out;
    float* out_v      = out_hidden + (size_t)Nn * Dk;
    float* out_mu     = out_v + (size_t)Nn * Dk;

    float* h1   = sym(g_h1);
    float* qb   = sym(g_q);
    float* kb   = sym(g_k);
    float* vb   = sym(g_v);
    float* ob   = sym(g_o);
    float* op   = sym(g_oproj);
    float* ctrl = sym(g_ctrl);
    float* co   = sym(g_co);
    float* h2   = sym(g_hidden2);
    float* x2   = sym(g_x2);
    float* midg = sym(g_midg);
    float* midu = sym(g_midu);
    float* mid  = sym(g_mid);

    // 1) rmsnorm1
    rmsnorm_kernel<<<Nn, 256>>>(hidden, ln1_w, h1);

    // 2) QKV = h1@W + mu_prev@W_mu  (tf32 mma, dual pass)
    mma_gemm_kernel<false, true, false, 128, 0><<<dim3(Hh * DHd / 128, Nn / 128), 256>>>(
        h1, wq, mu_prev, w_mu_q, nullptr, nullptr, qb, Hh * DHd, Dk, Dk, Hh * DHd);
    mma_gemm_kernel<false, true, false, 128, 0><<<dim3(KVh * DHd / 128, Nn / 128), 256>>>(
        h1, wk, mu_prev, w_mu_k, nullptr, nullptr, kb, KVh * DHd, Dk, Dk, KVh * DHd);
    mma_gemm_kernel<false, true, false, 128, 0><<<dim3(KVh * DHd / 128, Nn / 128), 256>>>(
        h1, wv, mu_prev, w_mu_v, nullptr, nullptr, vb, KVh * DHd, Dk, Dk, KVh * DHd);

    // 3) q/k norm + rope (in place)
    qknorm_rope_kernel<<<dim3(Nn, Hh + KVh), 32>>>(qb, kb, positions, qnorm_w, knorm_w);

    // 4) attention (fp32, parallel softmax + fast exp)
    attn_kernel<<<dim3(Nn / 32, Hh), 256>>>(qb, kb, vb, ob);

    // 5) o-proj (tf32)
    mma_gemm_kernel<false, false, false, 128, 0><<<dim3(Dk / 128, Nn / 128), 256>>>(
        ob, wo, nullptr, nullptr, nullptr, nullptr, op, Dk, Hh * DHd, Hh * DHd, Dk);

    // 6) mu_cur = dyn_mu + oproj @ dyn_mu_proj_w (tf32, direct to output)
    mma_gemm_kernel<false, false, false, 128, 0><<<dim3(Dk / 128, Nn / 128), 256>>>(
        op, dyn_mu_proj_w, nullptr, nullptr, dyn_mu, nullptr, out_mu, Dk, Dk, Dk, Dk);

    // 7) ctrl = silu([o, velocity] @ ctrl_in_w + b)  (tf32 BN=64, dual, silu)
    mma_gemm_kernel<false, true, false, 64, 1><<<dim3(1, Nn / 128), 256>>>(
        op, ctrl_in_w, velocity, ctrl_in_w + (size_t)Dk * CHc, ctrl_in_b, nullptr,
        ctrl, CHc, Dk, Dk, CHc);

    // 8) co = ctrl @ ctrl_out_w + b  (tf32, K=64)
    mma_gemm_kernel<false, false, false, 128, 0><<<dim3(3 * Dk / 128, Nn / 128), 256>>>(
        ctrl, ctrl_out_w, nullptr, nullptr, ctrl_out_b, nullptr, co, 3 * Dk, CHc, CHc, 3 * Dk);

    // 9) dynamics: v_next (output), hidden2
    dynamics_kernel<<<(Nn * Dk / 4 + 255) / 256, 256>>>((const float4*)hidden, (const float4*)velocity,
                                                        (const float4*)op, (const float4*)out_mu, co,
                                                        (float4*)out_v, (float4*)h2);

    // 10) rmsnorm2
    rmsnorm_kernel<<<Nn, 256>>>(h2, ln2_w, x2);

    // 11) router
    reset_counts_kernel<<<1, 32>>>();
    router_kernel<<<(Nn * 32 + 255) / 256, 256>>>(out_mu, mu_router_w, token_ids);

    // 12) MoE gate & up (tf32, gathered)
    mma_gemm_kernel<true, false, false, 128, 0><<<dim3(Ff / 128, Nn / 128, Ee), 256>>>(
        x2, w_gate, nullptr, nullptr, nullptr, nullptr, midg, Ff, Dk, Dk, Ff);
    mma_gemm_kernel<true, false, false, 128, 0><<<dim3(Ff / 128, Nn / 128, Ee), 256>>>(
        x2, w_up, nullptr, nullptr, nullptr, nullptr, midu, Ff, Dk, Dk, Ff);

    // 12b) mid = silu(g) * u
    silumul_kernel<<<(Nn * Ff / 4 + 255) / 256, 256>>>((const float4*)midg, (const float4*)midu,
                                                       (float4*)mid);

    // 13) MoE down + residual -> final hidden (tf32, gathered)
    mma_gemm_kernel<true, false, true, 128, 0><<<dim3(Dk / 128, Nn / 128, Ee), 256>>>(
        mid, w_down, nullptr, nullptr, nullptr, h2, out_hidden, Dk, Ff, Ff, Dk);
}

// round 10
// speedup vs baseline: 4.0546x; 1.5863x over previous
#include <cuda_runtime.h>
#include <cuda_bf16.h>
#include <cstdint>
#include <cmath>

// Problem constants
constexpr int Nn  = 2048;   // tokens
constexpr int Dk  = 1024;   // model dim
constexpr int Hh  = 16;     // q heads
constexpr int KVh = 4;      // kv heads
constexpr int DHd = 64;     // head dim
constexpr int Ee  = 8;      // experts
constexpr int Ff  = 2048;   // ffn dim
constexpr int CHc = 64;     // ctrl hidden
constexpr float EPS = 1e-6f;
constexpr float DT  = 0.1f;
constexpr float BASE_SCALE = 10.0f;

// ---------------- device scratch (static, allowed) ----------------
__device__ float g_h1[Nn * Dk];
__device__ float g_q[Nn * Hh * DHd];
__device__ float g_k[Nn * KVh * DHd];
__device__ float g_v[Nn * KVh * DHd];
__device__ float g_o[Nn * Hh * DHd];
__device__ float g_oproj[Nn * Dk];
__device__ float g_ctrl[Nn * CHc];
__device__ float g_co[Nn * 3 * Dk];
__device__ float g_hidden2[Nn * Dk];
__device__ float g_x2[Nn * Dk];
__device__ float g_midg[Nn * Ff];
__device__ float g_midu[Nn * Ff];
__device__ float g_mid[Nn * Ff];
__device__ int   g_counts[Ee];
__device__ int   g_list[Ee * Nn];

// ---------------- tf32 helpers ----------------
__device__ __forceinline__ uint32_t cvt_tf32(float x) {
    uint32_t r;
    asm("cvt.rna.tf32.f32 %0, %1;" : "=r"(r) : "f"(x));
    return r;
}

__device__ __forceinline__ void mma_tf32(float c[4],
    uint32_t a0, uint32_t a1, uint32_t a2, uint32_t a3,
    uint32_t b0, uint32_t b1)
{
    asm volatile("mma.sync.aligned.m16n8k8.row.col.f32.tf32.tf32.f32 "
        "{%0,%1,%2,%3}, {%4,%5,%6,%7}, {%8,%9}, {%0,%1,%2,%3};"
        : "+f"(c[0]), "+f"(c[1]), "+f"(c[2]), "+f"(c[3])
        : "r"(a0), "r"(a1), "r"(a2), "r"(a3), "r"(b0), "r"(b1));
}

// fast exp via 2^f polynomial (rel err ~8e-6)
__device__ __forceinline__ float fexp(float x) {
    float t = x * 1.442695040888963f;
    t = fmaxf(t, -126.0f);
    int i = __float2int_rd(t);
    float f = t - (float)i;
    float p =         1.540353039e-4f;
    p = fmaf(p, f, 1.333355815e-3f);
    p = fmaf(p, f, 9.618129108e-3f);
    p = fmaf(p, f, 5.550410866e-2f);
    p = fmaf(p, f, 2.402265070e-1f);
    p = fmaf(p, f, 6.931471806e-1f);
    p = fmaf(p, f, 1.0f);
    return p * __int_as_float((i + 127) << 23);
}

// ============================================================================
// Unified tf32 tensor-core GEMM: C[M,N] = act(A@B (+A2@B2) (+bias)) (+res)
// BM=128, BN=128 or 64, BK=16, 256 threads, double-buffered smem.
// ============================================================================
template<bool GATHER, bool DUAL, bool RES, int BN, int ACT>
__global__ __launch_bounds__(256, 1)
void mma_gemm_kernel(const float* __restrict__ A, const float* __restrict__ Bw,
                     const float* __restrict__ A2, const float* __restrict__ B2,
                     const float* __restrict__ bias, const float* __restrict__ res,
                     float* __restrict__ C, int N, int K, int lda, int ldc)
{
    constexpr int MT = (BN == 128) ? 4 : 2;
    __shared__ uint32_t As[2][16][136];
    __shared__ uint32_t Bs[2][16][BN + 8];
    __shared__ int toks[128];

    const float* B = Bw;
    int row0 = blockIdx.y * 128;
    if (GATHER) {
        int e = blockIdx.z;
        int cnt = g_counts[e];
        if (row0 >= cnt) return;
        B += (size_t)e * K * N;
        if (threadIdx.x < 128) {
            int idx = row0 + threadIdx.x;
            toks[threadIdx.x] = (idx < cnt) ? g_list[e * Nn + idx] : -1;
        }
        __syncthreads();
    }
    int col0 = blockIdx.x * BN;
    int tid  = threadIdx.x;
    int lane = tid & 31, warp = tid >> 5;
    int grp = lane >> 2, tig = lane & 3;
    int wm = (BN == 128) ? (warp >> 2) * 64 : (warp >> 1) * 32;
    int wn = (BN == 128) ? (warp & 3) * 32 : (warp & 1) * 32;

    int rowA = tid >> 1, colA = (tid & 1) << 3;
    int rB128 = tid >> 5, cB128 = (lane) << 2;
    int rB64  = tid >> 4, cB64  = (tid & 15) << 2;

    long aRow = GATHER ? (long)toks[rowA] : (long)(row0 + rowA);

    float c[MT][4][4];
    #pragma unroll
    for (int i = 0; i < MT; i++)
        #pragma unroll
        for (int j = 0; j < 4; j++)
            #pragma unroll
            for (int l = 0; l < 4; l++) c[i][j][l] = 0.f;

    const int TK = K / 16;
    const int T = (DUAL ? 2 : 1) * TK;
    float4 pa0, pa1, pb0, pb1;

    auto ldg = [&](int t) {
        int pass = DUAL ? (t >= TK) : 0;
        int k0 = (pass ? t - TK : t) << 4;
        const float* Ap = pass ? A2 : A;
        const float* Bp = pass ? B2 : B;
        if (!GATHER || aRow >= 0) {
            const float* ar = Ap + (size_t)aRow * lda + k0 + colA;
            pa0 = *(const float4*)ar;
            pa1 = *(const float4*)(ar + 4);
        } else {
            pa0 = make_float4(0, 0, 0, 0);
            pa1 = make_float4(0, 0, 0, 0);
        }
        if (BN == 128) {
            pb0 = *(const float4*)&Bp[(size_t)(k0 + rB128) * N + col0 + cB128];
            pb1 = *(const float4*)&Bp[(size_t)(k0 + rB128 + 8) * N + col0 + cB128];
        } else {
            pb0 = *(const float4*)&Bp[(size_t)(k0 + rB64) * N + col0 + cB64];
        }
    };
    auto sts = [&](int db) {
        As[db][colA + 0][rowA] = cvt_tf32(pa0.x);
        As[db][colA + 1][rowA] = cvt_tf32(pa0.y);
        As[db][colA + 2][rowA] = cvt_tf32(pa0.z);
        As[db][colA + 3][rowA] = cvt_tf32(pa0.w);
        As[db][colA + 4][rowA] = cvt_tf32(pa1.x);
        As[db][colA + 5][rowA] = cvt_tf32(pa1.y);
        As[db][colA + 6][rowA] = cvt_tf32(pa1.z);
        As[db][colA + 7][rowA] = cvt_tf32(pa1.w);
        if (BN == 128) {
            Bs[db][rB128][cB128 + 0] = cvt_tf32(pb0.x);
            Bs[db][rB128][cB128 + 1] = cvt_tf32(pb0.y);
            Bs[db][rB128][cB128 + 2] = cvt_tf32(pb0.z);
            Bs[db][rB128][cB128 + 3] = cvt_tf32(pb0.w);
            Bs[db][rB128 + 8][cB128 + 0] = cvt_tf32(pb1.x);
            Bs[db][rB128 + 8][cB128 + 1] = cvt_tf32(pb1.y);
            Bs[db][rB128 + 8][cB128 + 2] = cvt_tf32(pb1.z);
            Bs[db][rB128 + 8][cB128 + 3] = cvt_tf32(pb1.w);
        } else {
            Bs[db][rB64][cB64 + 0] = cvt_tf32(pb0.x);
            Bs[db][rB64][cB64 + 1] = cvt_tf32(pb0.y);
            Bs[db][rB64][cB64 + 2] = cvt_tf32(pb0.z);
            Bs[db][rB64][cB64 + 3] = cvt_tf32(pb0.w);
        }
    };
    auto compute = [&](int db) {
        #pragma unroll
        for (int ks = 0; ks < 16; ks += 8) {
            uint32_t af[MT][4], bf[4][2];
            #pragma unroll
            for (int mt = 0; mt < MT; ++mt) {
                int m = wm + mt * 16 + grp;
                af[mt][0] = As[db][ks + tig][m];
                af[mt][1] = As[db][ks + tig][m + 8];
                af[mt][2] = As[db][ks + tig + 4][m];
                af[mt][3] = As[db][ks + tig + 4][m + 8];
            }
            #pragma unroll
            for (int nt = 0; nt < 4; ++nt) {
                int n = wn + nt * 8 + grp;
                bf[nt][0] = Bs[db][ks + tig][n];
                bf[nt][1] = Bs[db][ks + tig + 4][n];
            }
            #pragma unroll
            for (int mt = 0; mt < MT; ++mt)
                #pragma unroll
                for (int nt = 0; nt < 4; ++nt)
                    mma_tf32(c[mt][nt], af[mt][0], af[mt][1], af[mt][2], af[mt][3],
                             bf[nt][0], bf[nt][1]);
        }
    };

    ldg(0);
    sts(0);
    if (T > 1) ldg(1);
    __syncthreads();
    for (int t = 0; t < T; ++t) {
        if (t + 1 < T) sts((t + 1) & 1);
        if (t + 2 < T) ldg(t + 2);
        compute(t & 1);
        __syncthreads();
    }

    #pragma unroll
    for (int mt = 0; mt < MT; ++mt) {
        #pragma unroll
        for (int h = 0; h < 2; ++h) {
            int rl = wm + mt * 16 + grp + h * 8;
            long orow;
            if (GATHER) {
                int tk = toks[rl];
                if (tk < 0) continue;
                orow = tk;
            } else {
                orow = row0 + rl;
            }
            #pragma unroll
            for (int nt = 0; nt < 4; ++nt) {
                int cg = col0 + wn + nt * 8 + tig * 2;
                float v0 = c[mt][nt][h * 2 + 0];
                float v1 = c[mt][nt][h * 2 + 1];
                if (bias) { v0 += bias[cg]; v1 += bias[cg + 1]; }
                if (ACT == 1) {
                    v0 = v0 / (1.f + expf(-v0));
                    v1 = v1 / (1.f + expf(-v1));
                }
                if (RES)  { v0 += res[orow * ldc + cg]; v1 += res[orow * ldc + cg + 1]; }
                *(float2*)&C[orow * ldc + cg] = make_float2(v0, v1);
            }
        }
    }
}

// ============================================================================
// Fused QKV tf32 GEMM: per-bx routing. 12 x-blocks: 8 Q, 2 K, 2 V. DUAL pass.
// ============================================================================
__global__ __launch_bounds__(256, 1)
void qkv_mma_kernel(const float* __restrict__ h1, const float* __restrict__ mu,
                    const float* __restrict__ wq, const float* __restrict__ wmq,
                    const float* __restrict__ wk, const float* __restrict__ wmk,
                    const float* __restrict__ wv, const float* __restrict__ wmv,
                    float* __restrict__ qo, float* __restrict__ ko, float* __restrict__ vo)
{
    __shared__ uint32_t As[2][16][136];
    __shared__ uint32_t Bs[2][16][136];
    int bx = blockIdx.x;
    const float *B0, *B1; float* Cp; int Nout, colbase;
    if (bx < 8)       { B0 = wq; B1 = wmq; Cp = qo; Nout = 1024; colbase = bx * 128; }
    else if (bx < 10) { B0 = wk; B1 = wmk; Cp = ko; Nout = 256;  colbase = (bx - 8) * 128; }
    else              { B0 = wv; B1 = wmv; Cp = vo; Nout = 256;  colbase = (bx - 10) * 128; }
    int row0 = blockIdx.y * 128;
    int tid  = threadIdx.x;
    int lane = tid & 31, warp = tid >> 5;
    int grp = lane >> 2, tig = lane & 3;
    int wm = (warp >> 2) * 64;
    int wn = (warp & 3) * 32;
    int rowA = tid >> 1, colA = (tid & 1) << 3;
    int rB = tid >> 5, cB = lane << 2;

    float c[4][4][4];
    #pragma unroll
    for (int i = 0; i < 4; i++)
        #pragma unroll
        for (int j = 0; j < 4; j++)
            #pragma unroll
            for (int l = 0; l < 4; l++) c[i][j][l] = 0.f;

    const int TK = Dk / 16;        // 64
    const int T = 2 * TK;          // 128
    float4 pa0, pa1, pb0, pb1;
    auto ldg = [&](int t) {
        int pass = (t >= TK);
        int k0 = (pass ? t - TK : t) << 4;
        const float* Ap = pass ? mu : h1;
        const float* Bp = pass ? B1 : B0;
        const float* ar = Ap + (size_t)(row0 + rowA) * Dk + k0 + colA;
        pa0 = *(const float4*)ar;
        pa1 = *(const float4*)(ar + 4);
        pb0 = *(const float4*)&Bp[(size_t)(k0 + rB) * Nout + colbase + cB];
        pb1 = *(const float4*)&Bp[(size_t)(k0 + rB + 8) * Nout + colbase + cB];
    };
    auto sts = [&](int db) {
        As[db][colA + 0][rowA] = cvt_tf32(pa0.x);
        As[db][colA + 1][rowA] = cvt_tf32(pa0.y);
        As[db][colA + 2][rowA] = cvt_tf32(pa0.z);
        As[db][colA + 3][rowA] = cvt_tf32(pa0.w);
        As[db][colA + 4][rowA] = cvt_tf32(pa1.x);
        As[db][colA + 5][rowA] = cvt_tf32(pa1.y);
        As[db][colA + 6][rowA] = cvt_tf32(pa1.z);
        As[db][colA + 7][rowA] = cvt_tf32(pa1.w);
        Bs[db][rB][cB + 0] = cvt_tf32(pb0.x);
        Bs[db][rB][cB + 1] = cvt_tf32(pb0.y);
        Bs[db][rB][cB + 2] = cvt_tf32(pb0.z);
        Bs[db][rB][cB + 3] = cvt_tf32(pb0.w);
        Bs[db][rB + 8][cB + 0] = cvt_tf32(pb1.x);
        Bs[db][rB + 8][cB + 1] = cvt_tf32(pb1.y);
        Bs[db][rB + 8][cB + 2] = cvt_tf32(pb1.z);
        Bs[db][rB + 8][cB + 3] = cvt_tf32(pb1.w);
    };
    auto compute = [&](int db) {
        #pragma unroll
        for (int ks = 0; ks < 16; ks += 8) {
            uint32_t af[4][4], bf[4][2];
            #pragma unroll
            for (int mt = 0; mt < 4; ++mt) {
                int m = wm + mt * 16 + grp;
                af[mt][0] = As[db][ks + tig][m];
                af[mt][1] = As[db][ks + tig][m + 8];
                af[mt][2] = As[db][ks + tig + 4][m];
                af[mt][3] = As[db][ks + tig + 4][m + 8];
            }
            #pragma unroll
            for (int nt = 0; nt < 4; ++nt) {
                int n = wn + nt * 8 + grp;
                bf[nt][0] = Bs[db][ks + tig][n];
                bf[nt][1] = Bs[db][ks + tig + 4][n];
            }
            #pragma unroll
            for (int mt = 0; mt < 4; ++mt)
                #pragma unroll
                for (int nt = 0; nt < 4; ++nt)
                    mma_tf32(c[mt][nt], af[mt][0], af[mt][1], af[mt][2], af[mt][3],
                             bf[nt][0], bf[nt][1]);
        }
    };
    ldg(0);
    sts(0);
    ldg(1);
    __syncthreads();
    for (int t = 0; t < T; ++t) {
        if (t + 1 < T) sts((t + 1) & 1);
        if (t + 2 < T) ldg(t + 2);
        compute(t & 1);
        __syncthreads();
    }
    #pragma unroll
    for (int mt = 0; mt < 4; ++mt) {
        #pragma unroll
        for (int h = 0; h < 2; ++h) {
            int rl = wm + mt * 16 + grp + h * 8;
            long orow = row0 + rl;
            #pragma unroll
            for (int nt = 0; nt < 4; ++nt) {
                int cg = colbase + wn + nt * 8 + tig * 2;
                *(float2*)&Cp[orow * Nout + cg] =
                    make_float2(c[mt][nt][h * 2 + 0], c[mt][nt][h * 2 + 1]);
            }
        }
    }
}

// ============================================================================
// Tensor-core flash attention: tf32 mma for S=QK^T and O=PV, fp32 softmax.
// 32 q-rows/CTA, 64-key tiles, 8 warps (warp tile 16x16).
// ============================================================================
__global__ __launch_bounds__(256, 1)
void attn_mma_kernel(const float* __restrict__ q, const float* __restrict__ k,
                     const float* __restrict__ v, float* __restrict__ o)
{
    __shared__ uint32_t Qs[32][68];    // tf32 bits, row-major [q][d]
    __shared__ float KVs[64][68];      // K then V tile, row-major [key][d]
    __shared__ float Ss[32][68];       // scores -> probabilities
    __shared__ float mrow[32], lrow[32], crow[32];

    int h = blockIdx.y;
    int kvh = h >> 2;
    int q0 = blockIdx.x * 32;
    int tid = threadIdx.x;
    int lane = tid & 31, warp = tid >> 5;
    int grp = lane >> 2, tig = lane & 3;
    int wm = (warp >> 2) * 16;    // 0 or 16
    int wn = (warp & 3) * 16;     // 0,16,32,48
    int sr = tid >> 3, t8 = tid & 7;
    int vr = tid >> 2, vc = (tid & 3) * 16;   // KV loader: row, col base

    // load Q (convert to tf32 once)
    {
        int r = tid >> 3, c0 = (tid & 7) * 8;
        const float* src = q + ((size_t)(q0 + r) * Hh + h) * DHd + c0;
        float4 x0 = *(const float4*)src;
        float4 x1 = *(const float4*)(src + 4);
        Qs[r][c0 + 0] = cvt_tf32(x0.x);
        Qs[r][c0 + 1] = cvt_tf32(x0.y);
        Qs[r][c0 + 2] = cvt_tf32(x0.z);
        Qs[r][c0 + 3] = cvt_tf32(x0.w);
        Qs[r][c0 + 4] = cvt_tf32(x1.x);
        Qs[r][c0 + 5] = cvt_tf32(x1.y);
        Qs[r][c0 + 6] = cvt_tf32(x1.z);
        Qs[r][c0 + 7] = cvt_tf32(x1.w);
    }
    if (tid < 32) { mrow[tid] = -1e30f; lrow[tid] = 0.f; }

    float acc[2][4];
    #pragma unroll
    for (int nt = 0; nt < 2; ++nt)
        #pragma unroll
        for (int l = 0; l < 4; ++l) acc[nt][l] = 0.f;

    // prefetch K tile 0
    float4 kpre[4];
    {
        const float* src = k + ((size_t)(0 + vr) * KVh + kvh) * DHd + vc;
        kpre[0] = *(const float4*)(src);
        kpre[1] = *(const float4*)(src + 4);
        kpre[2] = *(const float4*)(src + 8);
        kpre[3] = *(const float4*)(src + 12);
    }
    __syncthreads();

    const int NT = Nn / 64;   // 32
    for (int kt = 0; kt < NT; ++kt) {
        // STS K
        *(float4*)&KVs[vr][vc + 0]  = kpre[0];
        *(float4*)&KVs[vr][vc + 4]  = kpre[1];
        *(float4*)&KVs[vr][vc + 8]  = kpre[2];
        *(float4*)&KVs[vr][vc + 12] = kpre[3];
        __syncthreads();

        // S = Q @ K^T  (per warp: 16 rows x 16 cols)
        float cs[2][4];
        #pragma unroll
        for (int nt = 0; nt < 2; ++nt)
            #pragma unroll
            for (int l = 0; l < 4; ++l) cs[nt][l] = 0.f;
        #pragma unroll
        for (int ks = 0; ks < 64; ks += 8) {
            uint32_t a0 = Qs[wm + grp][ks + tig];
            uint32_t a1 = Qs[wm + grp + 8][ks + tig];
            uint32_t a2 = Qs[wm + grp][ks + tig + 4];
            uint32_t a3 = Qs[wm + grp + 8][ks + tig + 4];
            #pragma unroll
            for (int nt = 0; nt < 2; ++nt) {
                int n = wn + nt * 8 + grp;
                uint32_t b0 = cvt_tf32(KVs[n][ks + tig]);
                uint32_t b1 = cvt_tf32(KVs[n][ks + tig + 4]);
                mma_tf32(cs[nt], a0, a1, a2, a3, b0, b1);
            }
        }
        // write S (scaled) to smem
        #pragma unroll
        for (int nt = 0; nt < 2; ++nt) {
            int cg = wn + nt * 8 + tig * 2;
            Ss[wm + grp][cg]         = cs[nt][0] * 0.125f;
            Ss[wm + grp][cg + 1]     = cs[nt][1] * 0.125f;
            Ss[wm + grp + 8][cg]     = cs[nt][2] * 0.125f;
            Ss[wm + grp + 8][cg + 1] = cs[nt][3] * 0.125f;
        }
        __syncthreads();

        // phase: prefetch V + next K (LDG first), then softmax, then STS V
        float4 vpre[4];
        {
            const float* src = v + ((size_t)(kt * 64 + vr) * KVh + kvh) * DHd + vc;
            vpre[0] = *(const float4*)(src);
            vpre[1] = *(const float4*)(src + 4);
            vpre[2] = *(const float4*)(src + 8);
            vpre[3] = *(const float4*)(src + 12);
        }
        if (kt + 1 < NT) {
            const float* src = k + ((size_t)((kt + 1) * 64 + vr) * KVh + kvh) * DHd + vc;
            kpre[0] = *(const float4*)(src);
            kpre[1] = *(const float4*)(src + 4);
            kpre[2] = *(const float4*)(src + 8);
            kpre[3] = *(const float4*)(src + 12);
        }
        // parallel online softmax (8 lanes per row)
        {
            float mx = -1e30f;
            #pragma unroll
            for (int j = 0; j < 8; ++j) mx = fmaxf(mx, Ss[sr][t8 * 8 + j]);
            #pragma unroll
            for (int off = 1; off < 8; off <<= 1)
                mx = fmaxf(mx, __shfl_xor_sync(0xffffffffu, mx, off));
            float mold = mrow[sr];
            float mnew = fmaxf(mold, mx);
            float corr = fexp(mold - mnew);
            float lsum = 0.f;
            #pragma unroll
            for (int j = 0; j < 8; ++j) {
                float p = fexp(Ss[sr][t8 * 8 + j] - mnew);
                Ss[sr][t8 * 8 + j] = p;
                lsum += p;
            }
            #pragma unroll
            for (int off = 1; off < 8; off <<= 1)
                lsum += __shfl_xor_sync(0xffffffffu, lsum, off);
            __syncwarp();
            if (t8 == 0) {
                lrow[sr] = lrow[sr] * corr + lsum;
                mrow[sr] = mnew;
                crow[sr] = corr;
            }
        }
        // STS V (overwrites K; all S reads done at previous sync)
        *(float4*)&KVs[vr][vc + 0]  = vpre[0];
        *(float4*)&KVs[vr][vc + 4]  = vpre[1];
        *(float4*)&KVs[vr][vc + 8]  = vpre[2];
        *(float4*)&KVs[vr][vc + 12] = vpre[3];
        __syncthreads();

        // O = P @ V  (rescale then accumulate)
        float c0m = crow[wm + grp], c1m = crow[wm + grp + 8];
        #pragma unroll
        for (int nt = 0; nt < 2; ++nt) {
            acc[nt][0] *= c0m; acc[nt][1] *= c0m;
            acc[nt][2] *= c1m; acc[nt][3] *= c1m;
        }
        #pragma unroll
        for (int ks = 0; ks < 64; ks += 8) {
            uint32_t a0 = cvt_tf32(Ss[wm + grp][ks + tig]);
            uint32_t a1 = cvt_tf32(Ss[wm + grp + 8][ks + tig]);
            uint32_t a2 = cvt_tf32(Ss[wm + grp][ks + tig + 4]);
            uint32_t a3 = cvt_tf32(Ss[wm + grp + 8][ks + tig + 4]);
            #pragma unroll
            for (int nt = 0; nt < 2; ++nt) {
                int n = wn + nt * 8 + grp;
                uint32_t b0 = cvt_tf32(KVs[ks + tig][n]);
                uint32_t b1 = cvt_tf32(KVs[ks + tig + 4][n]);
                mma_tf32(acc[nt], a0, a1, a2, a3, b0, b1);
            }
        }
        __syncthreads();
    }

    // epilogue: divide by l, write
    float l0 = lrow[wm + grp], l1 = lrow[wm + grp + 8];
    #pragma unroll
    for (int nt = 0; nt < 2; ++nt) {
        int cg = wn + nt * 8 + tig * 2;
        int r0 = q0 + wm + grp;
        int r1 = r0 + 8;
        *(float2*)&o[((size_t)r0 * Hh + h) * DHd + cg] =
            make_float2(acc[nt][0] / l0, acc[nt][1] / l0);
        *(float2*)&o[((size_t)r1 * Hh + h) * DHd + cg] =
            make_float2(acc[nt][2] / l1, acc[nt][3] / l1);
    }
}

// ---------------- rmsnorm (float4 vectorized) ----------------
__global__ void rmsnorm_kernel(const float* __restrict__ x, const float* __restrict__ w,
                               float* __restrict__ y)
{
    int n = blockIdx.x;
    const float4* xr = (const float4*)(x + (size_t)n * Dk);
    const float4* wr = (const float4*)w;
    float4*       yr = (float4*)(y + (size_t)n * Dk);
    float s = 0.f;
    float4 v = xr[threadIdx.x];
    s = v.x * v.x + v.y * v.y + v.z * v.z + v.w * v.w;
    __shared__ float red[8];
    int lane = threadIdx.x & 31, wid = threadIdx.x >> 5;
    #pragma unroll
    for (int o = 16; o; o >>= 1) s += __shfl_xor_sync(0xffffffffu, s, o);
    if (lane == 0) red[wid] = s;
    __syncthreads();
    if (wid == 0) {
        float t = (lane < 8) ? red[lane] : 0.f;
        #pragma unroll
        for (int o = 4; o; o >>= 1) t += __shfl_xor_sync(0xffffffffu, t, o);
        if (lane == 0) red[0] = rsqrtf(t / Dk + EPS);
    }
    __syncthreads();
    float rms = red[0];
    float4 wv = wr[threadIdx.x];
    float4 out;
    out.x = v.x * rms * wv.x;
    out.y = v.y * rms * wv.y;
    out.z = v.z * rms * wv.z;
    out.w = v.w * rms * wv.w;
    yr[threadIdx.x] = out;
}

// ---------------- q/k rmsnorm + rope ----------------
__global__ void qknorm_rope_kernel(float* __restrict__ q, float* __restrict__ k,
                                   const int* __restrict__ positions,
                                   const float* __restrict__ qw, const float* __restrict__ kw)
{
    int n = blockIdx.x;
    int hh = blockIdx.y;
    float* x; const float* w;
    if (hh < Hh) { x = q + ((size_t)n * Hh + hh) * DHd; w = qw; }
    else         { x = k + ((size_t)n * KVh + (hh - Hh)) * DHd; w = kw; }
    int lane = threadIdx.x;
    float x1 = x[lane], x2 = x[lane + 32];
    float s = x1 * x1 + x2 * x2;
    #pragma unroll
    for (int o = 16; o; o >>= 1) s += __shfl_xor_sync(0xffffffffu, s, o);
    float rms = rsqrtf(s / 64.f + EPS);
    float v1 = x1 * rms * w[lane];
    float v2 = x2 * rms * w[lane + 32];
    float inv = (float)exp(-(2.0 * (double)lane / 64.0) * log(10000.0));
    float ang = (float)positions[n] * inv;
    float c = cosf(ang), sn = sinf(ang);
    x[lane]      = v1 * c - v2 * sn;
    x[lane + 32] = v2 * c + v1 * sn;
}

// ---------------- dynamics (elementwise, float4) ----------------
__global__ void dynamics_kernel(const float4* __restrict__ hidden_in,
                                const float4* __restrict__ velocity,
                                const float4* __restrict__ oproj,
                                const float4* __restrict__ mu,
                                const float* __restrict__ co,
                                float4* __restrict__ v_out,
                                float4* __restrict__ hidden2)
{
    int idx = blockIdx.x * blockDim.x + threadIdx.x;
    if (idx >= Nn * Dk / 4) return;
    int n = idx / (Dk / 4), c4 = idx - n * (Dk / 4);
    const float4* cr = (const float4*)(co + (size_t)n * 3 * Dk);
    float4 a_raw  = cr[c4];
    float4 b_raw  = cr[Dk / 4 + c4];
    float4 gt_raw = cr[2 * Dk / 4 + c4];
    float4 ov  = oproj[idx];
    float4 muv = mu[idx];
    float4 vel = velocity[idx];
    float4 hin = hidden_in[idx];
    float4 vn, h2;
    #pragma unroll
    for (int j = 0; j < 4; ++j) {
        float ar = (&a_raw.x)[j], br = (&b_raw.x)[j], gr = (&gt_raw.x)[j];
        float alpha = 1.f / (1.f + expf(-ar));
        float sp = (br > 20.f) ? br : log1pf(expf(br));
        float beta = fminf(sp, 2.f);
        float gate = 1.f / (1.f + expf(-gr));
        float o = (&ov.x)[j];
        float err = o - (&muv.x)[j];
        float vv = alpha * (&vel.x)[j] - beta * err;
        vv = fminf(fmaxf(vv, -10.f), 10.f);
        (&vn.x)[j] = vv;
        (&h2.x)[j] = (&hin.x)[j] + o + DT * gate * vv;
    }
    v_out[idx] = vn;
    hidden2[idx] = h2;
}

// ---------------- router ----------------
__global__ void reset_counts_kernel()
{
    if (threadIdx.x < Ee) g_counts[threadIdx.x] = 0;
}

__global__ void router_kernel(const float* __restrict__ mu, const float* __restrict__ W,
                              const int* __restrict__ token_ids)
{
    int gwarp = (blockIdx.x * blockDim.x + threadIdx.x) >> 5;
    int lane = threadIdx.x & 31;
    if (gwarp >= Nn) return;
    float acc[Ee] = {};
    const float* m = mu + (size_t)gwarp * Dk;
    for (int d = lane; d < Dk; d += 32) {
        float mv = m[d];
        #pragma unroll
        for (int e = 0; e < Ee; ++e) acc[e] += mv * W[d * Ee + e];
    }
    #pragma unroll
    for (int o = 16; o; o >>= 1)
        #pragma unroll
        for (int e = 0; e < Ee; ++e) acc[e] += __shfl_xor_sync(0xffffffffu, acc[e], o);
    if (lane == 0) {
        int base = token_ids[gwarp] % Ee;
        int best = 0; float bv = -1e30f;
        #pragma unroll
        for (int e = 0; e < Ee; ++e) {
            float vv = acc[e] + (e == base ? BASE_SCALE : 0.f);
            if (vv > bv) { bv = vv; best = e; }
        }
        int pos = atomicAdd(&g_counts[best], 1);
        g_list[best * Nn + pos] = gwarp;
    }
}

// ---------------- silu(g)*u elementwise ----------------
__global__ void silumul_kernel(const float4* __restrict__ G, const float4* __restrict__ U,
                               float4* __restrict__ Mid)
{
    int idx = blockIdx.x * blockDim.x + threadIdx.x;
    if (idx >= Nn * Ff / 4) return;
    float4 g = G[idx], u = U[idx], o;
    #pragma unroll
    for (int j = 0; j < 4; ++j) {
        float gv = (&g.x)[j];
        float sg = gv / (1.f + expf(-gv));
        (&o.x)[j] = sg * (&u.x)[j];
    }
    Mid[idx] = o;
}

// ---------------- launch ----------------
static float* sym(const void* s)
{
    void* p = nullptr;
    cudaGetSymbolAddress(&p, s);
    return (float*)p;
}

extern "C" void kernel_launch(void* const* d_in, const int* in_sizes, int n_in,
                              void* d_out, int out_size)
{
    const float* hidden        = (const float*)d_in[0];
    const int*   positions     = (const int*)  d_in[1];
    const float* velocity      = (const float*)d_in[2];
    const int*   token_ids     = (const int*)  d_in[3];
    const float* mu_prev       = (const float*)d_in[4];
    const float* ln1_w         = (const float*)d_in[5];
    const float* ln2_w         = (const float*)d_in[6];
    const float* wq            = (const float*)d_in[7];
    const float* wk            = (const float*)d_in[8];
    const float* wv            = (const float*)d_in[9];
    const float* wo            = (const float*)d_in[10];
    const float* w_mu_q        = (const float*)d_in[11];
    const float* w_mu_k        = (const float*)d_in[12];
    const float* w_mu_v        = (const float*)d_in[13];
    const float* qnorm_w       = (const float*)d_in[14];
    const float* knorm_w       = (const float*)d_in[15];
    const float* dyn_mu        = (const float*)d_in[16];
    const float* dyn_mu_proj_w = (const float*)d_in[17];
    const float* ctrl_in_w     = (const float*)d_in[18];
    const float* ctrl_in_b     = (const float*)d_in[19];
    const float* ctrl_out_w    = (const float*)d_in[20];
    const float* ctrl_out_b    = (const float*)d_in[21];
    const float* mu_router_w   = (const float*)d_in[22];
    const float* w_gate        = (const float*)d_in[23];
    const float* w_up          = (const float*)d_in[24];
    const float* w_down        = (const float*)d_in[25];

    float* out_hidden = (float*)d_out;
    float* out_v      = out_hidden + (size_t)Nn * Dk;
    float* out_mu     = out_v + (size_t)Nn * Dk;

    float* h1   = sym(g_h1);
    float* qb   = sym(g_q);
    float* kb   = sym(g_k);
    float* vb   = sym(g_v);
    float* ob   = sym(g_o);
    float* op   = sym(g_oproj);
    float* ctrl = sym(g_ctrl);
    float* co   = sym(g_co);
    float* h2   = sym(g_hidden2);
    float* x2   = sym(g_x2);
    float* midg = sym(g_midg);
    float* midu = sym(g_midu);
    float* mid  = sym(g_mid);

    // 1) rmsnorm1
    rmsnorm_kernel<<<Nn, 256>>>(hidden, ln1_w, h1);

    // 2) fused QKV = h1@W + mu_prev@W_mu  (tf32 mma, one launch, 192 CTAs)
    qkv_mma_kernel<<<dim3(12, Nn / 128), 256>>>(h1, mu_prev, wq, w_mu_q, wk, w_mu_k,
                                                wv, w_mu_v, qb, kb, vb);

    // 3) q/k norm + rope (in place)
    qknorm_rope_kernel<<<dim3(Nn, Hh + KVh), 32>>>(qb, kb, positions, qnorm_w, knorm_w);

    // 4) attention (tf32 mma)
    attn_mma_kernel<<<dim3(Nn / 32, Hh), 256>>>(qb, kb, vb, ob);

    // 5) o-proj (tf32)
    mma_gemm_kernel<false, false, false, 128, 0><<<dim3(Dk / 128, Nn / 128), 256>>>(
        ob, wo, nullptr, nullptr, nullptr, nullptr, op, Dk, Hh * DHd, Hh * DHd, Dk);

    // 6) mu_cur = dyn_mu + oproj @ dyn_mu_proj_w (tf32, direct to output)
    mma_gemm_kernel<false, false, false, 128, 0><<<dim3(Dk / 128, Nn / 128), 256>>>(
        op, dyn_mu_proj_w, nullptr, nullptr, dyn_mu, nullptr, out_mu, Dk, Dk, Dk, Dk);

    // 7) ctrl = silu([o, velocity] @ ctrl_in_w + b)  (tf32 BN=64, dual, silu)
    mma_gemm_kernel<false, true, false, 64, 1><<<dim3(1, Nn / 128), 256>>>(
        op, ctrl_in_w, velocity, ctrl_in_w + (size_t)Dk * CHc, ctrl_in_b, nullptr,
        ctrl, CHc, Dk, Dk, CHc);

    // 8) co = ctrl @ ctrl_out_w + b  (tf32, K=64)
    mma_gemm_kernel<false, false, false, 128, 0><<<dim3(3 * Dk / 128, Nn / 128), 256>>>(
        ctrl, ctrl_out_w, nullptr, nullptr, ctrl_out_b, nullptr, co, 3 * Dk, CHc, CHc, 3 * Dk);

    // 9) dynamics: v_next (output), hidden2
    dynamics_kernel<<<(Nn * Dk / 4 + 255) / 256, 256>>>((const float4*)hidden, (const float4*)velocity,
                                                        (const float4*)op, (const float4*)out_mu, co,
                                                        (float4*)out_v, (float4*)h2);

    // 10) rmsnorm2
    rmsnorm_kernel<<<Nn, 256>>>(h2, ln2_w, x2);

    // 11) router
    reset_counts_kernel<<<1, 32>>>();
    router_kernel<<<(Nn * 32 + 255) / 256, 256>>>(out_mu, mu_router_w, token_ids);

    // 12) MoE gate & up (tf32, gathered)
    mma_gemm_kernel<true, false, false, 128, 0><<<dim3(Ff / 128, Nn / 128, Ee), 256>>>(
        x2, w_gate, nullptr, nullptr, nullptr, nullptr, midg, Ff, Dk, Dk, Ff);
    mma_gemm_kernel<true, false, false, 128, 0><<<dim3(Ff / 128, Nn / 128, Ee), 256>>>(
        x2, w_up, nullptr, nullptr, nullptr, nullptr, midu, Ff, Dk, Dk, Ff);

    // 12b) mid = silu(g) * u
    silumul_kernel<<<(Nn * Ff / 4 + 255) / 256, 256>>>((const float4*)midg, (const float4*)midu,
                                                       (float4*)mid);

    // 13) MoE down + residual -> final hidden (tf32, gathered)
    mma_gemm_kernel<true, false, true, 128, 0><<<dim3(Dk / 128, Nn / 128, Ee), 256>>>(
        mid, w_down, nullptr, nullptr, nullptr, h2, out_hidden, Dk, Ff, Ff, Dk);
}

// round 14
// speedup vs baseline: 4.3902x; 1.0828x over previous
#include <cuda_runtime.h>
#include <cuda_bf16.h>
#include <cstdint>
#include <cmath>

// Problem constants
constexpr int Nn  = 2048;   // tokens
constexpr int Dk  = 1024;   // model dim
constexpr int Hh  = 16;     // q heads
constexpr int KVh = 4;      // kv heads
constexpr int DHd = 64;     // head dim
constexpr int Ee  = 8;      // experts
constexpr int Ff  = 2048;   // ffn dim
constexpr int CHc = 64;     // ctrl hidden
constexpr float EPS = 1e-6f;
constexpr float DT  = 0.1f;
constexpr float BASE_SCALE = 10.0f;

// ---------------- device scratch (static, allowed) ----------------
__device__ float g_h1[Nn * Dk];
__device__ float g_q[Nn * Hh * DHd];
__device__ float g_k[Nn * KVh * DHd];
__device__ float g_v[Nn * KVh * DHd];
__device__ float g_o[Nn * Hh * DHd];
__device__ float g_oproj[Nn * Dk];
__device__ float g_ctrl[Nn * CHc];
__device__ float g_co[Nn * 3 * Dk];
__device__ float g_hidden2[Nn * Dk];
__device__ float g_x2[Nn * Dk];
__device__ float g_midg[Nn * Ff];
__device__ float g_midu[Nn * Ff];
__device__ float g_mid[Nn * Ff];
__device__ int   g_counts[Ee];
__device__ int   g_list[Ee * Nn];

// ---------------- tf32 helpers ----------------
__device__ __forceinline__ uint32_t cvt_tf32(float x) {
    uint32_t r;
    asm("cvt.rna.tf32.f32 %0, %1;" : "=r"(r) : "f"(x));
    return r;
}

__device__ __forceinline__ void mma_tf32(float c[4],
    uint32_t a0, uint32_t a1, uint32_t a2, uint32_t a3,
    uint32_t b0, uint32_t b1)
{
    asm volatile("mma.sync.aligned.m16n8k8.row.col.f32.tf32.tf32.f32 "
        "{%0,%1,%2,%3}, {%4,%5,%6,%7}, {%8,%9}, {%0,%1,%2,%3};"
        : "+f"(c[0]), "+f"(c[1]), "+f"(c[2]), "+f"(c[3])
        : "r"(a0), "r"(a1), "r"(a2), "r"(a3), "r"(b0), "r"(b1));
}

// fast exp via 2^f polynomial (rel err ~8e-6)
__device__ __forceinline__ float fexp(float x) {
    float t = x * 1.442695040888963f;
    t = fmaxf(t, -126.0f);
    int i = __float2int_rd(t);
    float f = t - (float)i;
    float p =         1.540353039e-4f;
    p = fmaf(p, f, 1.333355815e-3f);
    p = fmaf(p, f, 9.618129108e-3f);
    p = fmaf(p, f, 5.550410866e-2f);
    p = fmaf(p, f, 2.402265070e-1f);
    p = fmaf(p, f, 6.931471806e-1f);
    p = fmaf(p, f, 1.0f);
    return p * __int_as_float((i + 127) << 23);
}

__device__ __forceinline__ void cp_async16(uint32_t saddr, const void* gptr) {
    asm volatile("cp.async.ca.shared.global [%0], [%1], 16;" :: "r"(saddr), "l"(gptr));
}
__device__ __forceinline__ void cp_commit() {
    asm volatile("cp.async.commit_group;");
}
__device__ __forceinline__ void cp_wait0() {
    asm volatile("cp.async.wait_group 0;");
}

// ============================================================================
// Unified tf32 tensor-core GEMM: C[M,N] = act(A@B (+A2@B2) (+bias)) (+res)
// BM=128, BN=128 or 64, BK=16, 256 threads, double-buffered smem.
// ============================================================================
template<bool GATHER, bool DUAL, bool RES, int BN, int ACT>
__global__ __launch_bounds__(256, 1)
void mma_gemm_kernel(const float* __restrict__ A, const float* __restrict__ Bw,
                     const float* __restrict__ A2, const float* __restrict__ B2,
                     const float* __restrict__ bias, const float* __restrict__ res,
                     float* __restrict__ C, int N, int K, int lda, int ldc)
{
    constexpr int MT = (BN == 128) ? 4 : 2;
    __shared__ uint32_t As[2][16][136];
    __shared__ uint32_t Bs[2][16][BN + 8];
    __shared__ int toks[128];

    const float* B = Bw;
    int row0 = blockIdx.y * 128;
    if (GATHER) {
        int e = blockIdx.z;
        int cnt = g_counts[e];
        if (row0 >= cnt) return;
        B += (size_t)e * K * N;
        if (threadIdx.x < 128) {
            int idx = row0 + threadIdx.x;
            toks[threadIdx.x] = (idx < cnt) ? g_list[e * Nn + idx] : -1;
        }
        __syncthreads();
    }
    int col0 = blockIdx.x * BN;
    int tid  = threadIdx.x;
    int lane = tid & 31, warp = tid >> 5;
    int grp = lane >> 2, tig = lane & 3;
    int wm = (BN == 128) ? (warp >> 2) * 64 : (warp >> 1) * 32;
    int wn = (BN == 128) ? (warp & 3) * 32 : (warp & 1) * 32;

    int rowA = tid >> 1, colA = (tid & 1) << 3;
    int rB128 = tid >> 5, cB128 = (lane) << 2;
    int rB64  = tid >> 4, cB64  = (tid & 15) << 2;

    long aRow = GATHER ? (long)toks[rowA] : (long)(row0 + rowA);

    float c[MT][4][4];
    #pragma unroll
    for (int i = 0; i < MT; i++)
        #pragma unroll
        for (int j = 0; j < 4; j++)
            #pragma unroll
            for (int l = 0; l < 4; l++) c[i][j][l] = 0.f;

    const int TK = K / 16;
    const int T = (DUAL ? 2 : 1) * TK;
    float4 pa0, pa1, pb0, pb1;

    auto ldg = [&](int t) {
        int pass = DUAL ? (t >= TK) : 0;
        int k0 = (pass ? t - TK : t) << 4;
        const float* Ap = pass ? A2 : A;
        const float* Bp = pass ? B2 : B;
        if (!GATHER || aRow >= 0) {
            const float* ar = Ap + (size_t)aRow * lda + k0 + colA;
            pa0 = *(const float4*)ar;
            pa1 = *(const float4*)(ar + 4);
        } else {
            pa0 = make_float4(0, 0, 0, 0);
            pa1 = make_float4(0, 0, 0, 0);
        }
        if (BN == 128) {
            pb0 = *(const float4*)&Bp[(size_t)(k0 + rB128) * N + col0 + cB128];
            pb1 = *(const float4*)&Bp[(size_t)(k0 + rB128 + 8) * N + col0 + cB128];
        } else {
            pb0 = *(const float4*)&Bp[(size_t)(k0 + rB64) * N + col0 + cB64];
        }
    };
    auto sts = [&](int db) {
        As[db][colA + 0][rowA] = cvt_tf32(pa0.x);
        As[db][colA + 1][rowA] = cvt_tf32(pa0.y);
        As[db][colA + 2][rowA] = cvt_tf32(pa0.z);
        As[db][colA + 3][rowA] = cvt_tf32(pa0.w);
        As[db][colA + 4][rowA] = cvt_tf32(pa1.x);
        As[db][colA + 5][rowA] = cvt_tf32(pa1.y);
        As[db][colA + 6][rowA] = cvt_tf32(pa1.z);
        As[db][colA + 7][rowA] = cvt_tf32(pa1.w);
        if (BN == 128) {
            Bs[db][rB128][cB128 + 0] = cvt_tf32(pb0.x);
            Bs[db][rB128][cB128 + 1] = cvt_tf32(pb0.y);
            Bs[db][rB128][cB128 + 2] = cvt_tf32(pb0.z);
            Bs[db][rB128][cB128 + 3] = cvt_tf32(pb0.w);
            Bs[db][rB128 + 8][cB128 + 0] = cvt_tf32(pb1.x);
            Bs[db][rB128 + 8][cB128 + 1] = cvt_tf32(pb1.y);
            Bs[db][rB128 + 8][cB128 + 2] = cvt_tf32(pb1.z);
            Bs[db][rB128 + 8][cB128 + 3] = cvt_tf32(pb1.w);
        } else {
            Bs[db][rB64][cB64 + 0] = cvt_tf32(pb0.x);
            Bs[db][rB64][cB64 + 1] = cvt_tf32(pb0.y);
            Bs[db][rB64][cB64 + 2] = cvt_tf32(pb0.z);
            Bs[db][rB64][cB64 + 3] = cvt_tf32(pb0.w);
        }
    };
    auto compute = [&](int db) {
        #pragma unroll
        for (int ks = 0; ks < 16; ks += 8) {
            uint32_t af[MT][4], bf[4][2];
            #pragma unroll
            for (int mt = 0; mt < MT; ++mt) {
                int m = wm + mt * 16 + grp;
                af[mt][0] = As[db][ks + tig][m];
                af[mt][1] = As[db][ks + tig][m + 8];
                af[mt][2] = As[db][ks + tig + 4][m];
                af[mt][3] = As[db][ks + tig + 4][m + 8];
            }
            #pragma unroll
            for (int nt = 0; nt < 4; ++nt) {
                int n = wn + nt * 8 + grp;
                bf[nt][0] = Bs[db][ks + tig][n];
                bf[nt][1] = Bs[db][ks + tig + 4][n];
            }
            #pragma unroll
            for (int mt = 0; mt < MT; ++mt)
                #pragma unroll
                for (int nt = 0; nt < 4; ++nt)
                    mma_tf32(c[mt][nt], af[mt][0], af[mt][1], af[mt][2], af[mt][3],
                             bf[nt][0], bf[nt][1]);
        }
    };

    ldg(0);
    sts(0);
    if (T > 1) ldg(1);
    __syncthreads();
    for (int t = 0; t < T; ++t) {
        if (t + 1 < T) sts((t + 1) & 1);
        if (t + 2 < T) ldg(t + 2);
        compute(t & 1);
        __syncthreads();
    }

    #pragma unroll
    for (int mt = 0; mt < MT; ++mt) {
        #pragma unroll
        for (int h = 0; h < 2; ++h) {
            int rl = wm + mt * 16 + grp + h * 8;
            long orow;
            if (GATHER) {
                int tk = toks[rl];
                if (tk < 0) continue;
                orow = tk;
            } else {
                orow = row0 + rl;
            }
            #pragma unroll
            for (int nt = 0; nt < 4; ++nt) {
                int cg = col0 + wn + nt * 8 + tig * 2;
                float v0 = c[mt][nt][h * 2 + 0];
                float v1 = c[mt][nt][h * 2 + 1];
                if (bias) { v0 += bias[cg]; v1 += bias[cg + 1]; }
                if (ACT == 1) {
                    v0 = v0 / (1.f + expf(-v0));
                    v1 = v1 / (1.f + expf(-v1));
                }
                if (RES)  { v0 += res[orow * ldc + cg]; v1 += res[orow * ldc + cg + 1]; }
                *(float2*)&C[orow * ldc + cg] = make_float2(v0, v1);
            }
        }
    }
}

// ============================================================================
// Fused QKV tf32 GEMM: per-bx routing. 12 x-blocks: 8 Q, 2 K, 2 V. DUAL pass.
// ============================================================================
__global__ __launch_bounds__(256, 1)
void qkv_mma_kernel(const float* __restrict__ h1, const float* __restrict__ mu,
                    const float* __restrict__ wq, const float* __restrict__ wmq,
                    const float* __restrict__ wk, const float* __restrict__ wmk,
                    const float* __restrict__ wv, const float* __restrict__ wmv,
                    float* __restrict__ qo, float* __restrict__ ko, float* __restrict__ vo)
{
    __shared__ uint32_t As[2][16][136];
    __shared__ uint32_t Bs[2][16][136];
    int bx = blockIdx.x;
    const float *B0, *B1; float* Cp; int Nout, colbase;
    if (bx < 8)       { B0 = wq; B1 = wmq; Cp = qo; Nout = 1024; colbase = bx * 128; }
    else if (bx < 10) { B0 = wk; B1 = wmk; Cp = ko; Nout = 256;  colbase = (bx - 8) * 128; }
    else              { B0 = wv; B1 = wmv; Cp = vo; Nout = 256;  colbase = (bx - 10) * 128; }
    int row0 = blockIdx.y * 128;
    int tid  = threadIdx.x;
    int lane = tid & 31, warp = tid >> 5;
    int grp = lane >> 2, tig = lane & 3;
    int wm = (warp >> 2) * 64;
    int wn = (warp & 3) * 32;
    int rowA = tid >> 1, colA = (tid & 1) << 3;
    int rB = tid >> 5, cB = lane << 2;

    float c[4][4][4];
    #pragma unroll
    for (int i = 0; i < 4; i++)
        #pragma unroll
        for (int j = 0; j < 4; j++)
            #pragma unroll
            for (int l = 0; l < 4; l++) c[i][j][l] = 0.f;

    const int TK = Dk / 16;        // 64
    const int T = 2 * TK;          // 128
    float4 pa0, pa1, pb0, pb1;
    auto ldg = [&](int t) {
        int pass = (t >= TK);
        int k0 = (pass ? t - TK : t) << 4;
        const float* Ap = pass ? mu : h1;
        const float* Bp = pass ? B1 : B0;
        const float* ar = Ap + (size_t)(row0 + rowA) * Dk + k0 + colA;
        pa0 = *(const float4*)ar;
        pa1 = *(const float4*)(ar + 4);
        pb0 = *(const float4*)&Bp[(size_t)(k0 + rB) * Nout + colbase + cB];
        pb1 = *(const float4*)&Bp[(size_t)(k0 + rB + 8) * Nout + colbase + cB];
    };
    auto sts = [&](int db) {
        As[db][colA + 0][rowA] = cvt_tf32(pa0.x);
        As[db][colA + 1][rowA] = cvt_tf32(pa0.y);
        As[db][colA + 2][rowA] = cvt_tf32(pa0.z);
        As[db][colA + 3][rowA] = cvt_tf32(pa0.w);
        As[db][colA + 4][rowA] = cvt_tf32(pa1.x);
        As[db][colA + 5][rowA] = cvt_tf32(pa1.y);
        As[db][colA + 6][rowA] = cvt_tf32(pa1.z);
        As[db][colA + 7][rowA] = cvt_tf32(pa1.w);
        Bs[db][rB][cB + 0] = cvt_tf32(pb0.x);
        Bs[db][rB][cB + 1] = cvt_tf32(pb0.y);
        Bs[db][rB][cB + 2] = cvt_tf32(pb0.z);
        Bs[db][rB][cB + 3] = cvt_tf32(pb0.w);
        Bs[db][rB + 8][cB + 0] = cvt_tf32(pb1.x);
        Bs[db][rB + 8][cB + 1] = cvt_tf32(pb1.y);
        Bs[db][rB + 8][cB + 2] = cvt_tf32(pb1.z);
        Bs[db][rB + 8][cB + 3] = cvt_tf32(pb1.w);
    };
    auto compute = [&](int db) {
        #pragma unroll
        for (int ks = 0; ks < 16; ks += 8) {
            uint32_t af[4][4], bf[4][2];
            #pragma unroll
            for (int mt = 0; mt < 4; ++mt) {
                int m = wm + mt * 16 + grp;
                af[mt][0] = As[db][ks + tig][m];
                af[mt][1] = As[db][ks + tig][m + 8];
                af[mt][2] = As[db][ks + tig + 4][m];
                af[mt][3] = As[db][ks + tig + 4][m + 8];
            }
            #pragma unroll
            for (int nt = 0; nt < 4; ++nt) {
                int n = wn + nt * 8 + grp;
                bf[nt][0] = Bs[db][ks + tig][n];
                bf[nt][1] = Bs[db][ks + tig + 4][n];
            }
            #pragma unroll
            for (int mt = 0; mt < 4; ++mt)
                #pragma unroll
                for (int nt = 0; nt < 4; ++nt)
                    mma_tf32(c[mt][nt], af[mt][0], af[mt][1], af[mt][2], af[mt][3],
                             bf[nt][0], bf[nt][1]);
        }
    };
    ldg(0);
    sts(0);
    ldg(1);
    __syncthreads();
    for (int t = 0; t < T; ++t) {
        if (t + 1 < T) sts((t + 1) & 1);
        if (t + 2 < T) ldg(t + 2);
        compute(t & 1);
        __syncthreads();
    }
    #pragma unroll
    for (int mt = 0; mt < 4; ++mt) {
        #pragma unroll
        for (int h = 0; h < 2; ++h) {
            int rl = wm + mt * 16 + grp + h * 8;
            long orow = row0 + rl;
            #pragma unroll
            for (int nt = 0; nt < 4; ++nt) {
                int cg = colbase + wn + nt * 8 + tig * 2;
                *(float2*)&Cp[orow * Nout + cg] =
                    make_float2(c[mt][nt][h * 2 + 0], c[mt][nt][h * 2 + 1]);
            }
        }
    }
}

// ============================================================================
// Tensor-core flash attention v3:
// 64 q-rows/CTA, 128 threads (4 warps), warp owns 16 rows x ALL 64 keys.
// Softmax entirely in registers (shfl over tig lanes). Q frags in registers.
// P staged through smem as tf32 for the PV transpose. K/V via cp.async.
// ============================================================================
__global__ __launch_bounds__(128, 1)
void attn_mma_kernel(const float* __restrict__ q, const float* __restrict__ k,
                     const float* __restrict__ v, float* __restrict__ o)
{
    __shared__ float    KVf[64][68];   // K then V tile (raw fp32) 17.4 KB
    __shared__ uint32_t Ps[64][68];    // Q staging (tf32) then P (tf32) 17.4 KB

    int h = blockIdx.y;
    int kvh = h >> 2;
    int q0 = blockIdx.x * 64;
    int tid = threadIdx.x;
    int lane = tid & 31, warp = tid >> 5;
    int grp = lane >> 2, tig = lane & 3;
    int wr0 = warp * 16;                  // warp's q-row base
    int ldr = tid >> 1, ldc = (tid & 1) * 32;   // loader: row, col base (32 floats)

    uint32_t kv_s = (uint32_t)__cvta_generic_to_shared(&KVf[0][0]);

    // issue cp.async for K tile 0 early
    {
        const float* src = k + ((size_t)ldr * KVh + kvh) * DHd + ldc;
        uint32_t dst = kv_s + (ldr * 68 + ldc) * 4;
        #pragma unroll
        for (int i = 0; i < 8; ++i) cp_async16(dst + i * 16, src + i * 4);
        cp_commit();
    }

    // stage Q (tf32) into Ps
    {
        const float* src = q + ((size_t)(q0 + ldr) * Hh + h) * DHd + ldc;
        #pragma unroll
        for (int i = 0; i < 8; ++i) {
            float4 x = *(const float4*)(src + i * 4);
            Ps[ldr][ldc + i * 4 + 0] = cvt_tf32(x.x);
            Ps[ldr][ldc + i * 4 + 1] = cvt_tf32(x.y);
            Ps[ldr][ldc + i * 4 + 2] = cvt_tf32(x.z);
            Ps[ldr][ldc + i * 4 + 3] = cvt_tf32(x.w);
        }
    }
    __syncthreads();

    // Q fragments -> registers (32 regs)
    uint32_t qf[8][4];
    #pragma unroll
    for (int ks = 0; ks < 8; ++ks) {
        qf[ks][0] = Ps[wr0 + grp][ks * 8 + tig];
        qf[ks][1] = Ps[wr0 + grp + 8][ks * 8 + tig];
        qf[ks][2] = Ps[wr0 + grp][ks * 8 + tig + 4];
        qf[ks][3] = Ps[wr0 + grp + 8][ks * 8 + tig + 4];
    }

    float m0 = -1e30f, m1 = -1e30f, l0 = 0.f, l1 = 0.f;
    float acc[8][4];
    #pragma unroll
    for (int dt = 0; dt < 8; ++dt)
        #pragma unroll
        for (int l = 0; l < 4; ++l) acc[dt][l] = 0.f;

    const int NT = Nn / 64;   // 32
    for (int kt = 0; kt < NT; ++kt) {
        cp_wait0();
        __syncthreads();      // K tile ready; Q frag reads done (first iter)

        // ---- S = Q @ K^T : per warp 16 rows x 64 cols in registers ----
        float cs[8][4];
        #pragma unroll
        for (int nt = 0; nt < 8; ++nt)
            #pragma unroll
            for (int l = 0; l < 4; ++l) cs[nt][l] = 0.f;
        #pragma unroll
        for (int ks = 0; ks < 8; ++ks) {
            #pragma unroll
            for (int nt = 0; nt < 8; ++nt) {
                uint32_t b0 = cvt_tf32(KVf[nt * 8 + grp][ks * 8 + tig]);
                uint32_t b1 = cvt_tf32(KVf[nt * 8 + grp][ks * 8 + tig + 4]);
                mma_tf32(cs[nt], qf[ks][0], qf[ks][1], qf[ks][2], qf[ks][3], b0, b1);
            }
        }

        // ---- register softmax (rows wr0+grp and wr0+grp+8) ----
        float mx0 = -1e30f, mx1 = -1e30f;
        #pragma unroll
        for (int nt = 0; nt < 8; ++nt) {
            cs[nt][0] *= 0.125f; cs[nt][1] *= 0.125f;
            cs[nt][2] *= 0.125f; cs[nt][3] *= 0.125f;
            mx0 = fmaxf(mx0, fmaxf(cs[nt][0], cs[nt][1]));
            mx1 = fmaxf(mx1, fmaxf(cs[nt][2], cs[nt][3]));
        }
        mx0 = fmaxf(mx0, __shfl_xor_sync(0xffffffffu, mx0, 1));
        mx0 = fmaxf(mx0, __shfl_xor_sync(0xffffffffu, mx0, 2));
        mx1 = fmaxf(mx1, __shfl_xor_sync(0xffffffffu, mx1, 1));
        mx1 = fmaxf(mx1, __shfl_xor_sync(0xffffffffu, mx1, 2));
        float mnew0 = fmaxf(m0, mx0), mnew1 = fmaxf(m1, mx1);
        float corr0 = fexp(m0 - mnew0), corr1 = fexp(m1 - mnew1);
        float ls0 = 0.f, ls1 = 0.f;
        #pragma unroll
        for (int nt = 0; nt < 8; ++nt) {
            float p00 = fexp(cs[nt][0] - mnew0);
            float p01 = fexp(cs[nt][1] - mnew0);
            float p10 = fexp(cs[nt][2] - mnew1);
            float p11 = fexp(cs[nt][3] - mnew1);
            ls0 += p00 + p01;
            ls1 += p10 + p11;
            int cg = nt * 8 + tig * 2;
            Ps[wr0 + grp][cg]         = cvt_tf32(p00);
            Ps[wr0 + grp][cg + 1]     = cvt_tf32(p01);
            Ps[wr0 + grp + 8][cg]     = cvt_tf32(p10);
            Ps[wr0 + grp + 8][cg + 1] = cvt_tf32(p11);
        }
        ls0 += __shfl_xor_sync(0xffffffffu, ls0, 1);
        ls0 += __shfl_xor_sync(0xffffffffu, ls0, 2);
        ls1 += __shfl_xor_sync(0xffffffffu, ls1, 1);
        ls1 += __shfl_xor_sync(0xffffffffu, ls1, 2);
        l0 = l0 * corr0 + ls0;  m0 = mnew0;
        l1 = l1 * corr1 + ls1;  m1 = mnew1;
        // rescale accumulator
        #pragma unroll
        for (int dt = 0; dt < 8; ++dt) {
            acc[dt][0] *= corr0; acc[dt][1] *= corr0;
            acc[dt][2] *= corr1; acc[dt][3] *= corr1;
        }
        __syncthreads();      // all K reads done; P visible

        // ---- load V into KVf (overwrites K) ----
        {
            const float* src = v + ((size_t)(kt * 64 + ldr) * KVh + kvh) * DHd + ldc;
            uint32_t dst = kv_s + (ldr * 68 + ldc) * 4;
            #pragma unroll
            for (int i = 0; i < 8; ++i) cp_async16(dst + i * 16, src + i * 4);
            cp_commit();
        }
        cp_wait0();
        __syncthreads();      // V ready

        // ---- O += P @ V ----
        #pragma unroll
        for (int ks = 0; ks < 8; ++ks) {
            uint32_t a0 = Ps[wr0 + grp][ks * 8 + tig];
            uint32_t a1 = Ps[wr0 + grp + 8][ks * 8 + tig];
            uint32_t a2 = Ps[wr0 + grp][ks * 8 + tig + 4];
            uint32_t a3 = Ps[wr0 + grp + 8][ks * 8 + tig + 4];
            #pragma unroll
            for (int dt = 0; dt < 8; ++dt) {
                uint32_t b0 = cvt_tf32(KVf[ks * 8 + tig][dt * 8 + grp]);
                uint32_t b1 = cvt_tf32(KVf[ks * 8 + tig + 4][dt * 8 + grp]);
                mma_tf32(acc[dt], a0, a1, a2, a3, b0, b1);
            }
        }
        __syncthreads();      // all V reads done

        // ---- prefetch next K ----
        if (kt + 1 < NT) {
            const float* src = k + ((size_t)((kt + 1) * 64 + ldr) * KVh + kvh) * DHd + ldc;
            uint32_t dst = kv_s + (ldr * 68 + ldc) * 4;
            #pragma unroll
            for (int i = 0; i < 8; ++i) cp_async16(dst + i * 16, src + i * 4);
            cp_commit();
        }
    }

    // epilogue
    float r0inv = 1.f / l0, r1inv = 1.f / l1;
    int row0g = q0 + wr0 + grp;
    int row1g = row0g + 8;
    #pragma unroll
    for (int dt = 0; dt < 8; ++dt) {
        int cg = dt * 8 + tig * 2;
        *(float2*)&o[((size_t)row0g * Hh + h) * DHd + cg] =
            make_float2(acc[dt][0] * r0inv, acc[dt][1] * r0inv);
        *(float2*)&o[((size_t)row1g * Hh + h) * DHd + cg] =
            make_float2(acc[dt][2] * r1inv, acc[dt][3] * r1inv);
    }
}

// ---------------- rmsnorm (float4 vectorized) ----------------
__global__ void rmsnorm_kernel(const float* __restrict__ x, const float* __restrict__ w,
                               float* __restrict__ y)
{
    int n = blockIdx.x;
    const float4* xr = (const float4*)(x + (size_t)n * Dk);
    const float4* wr = (const float4*)w;
    float4*       yr = (float4*)(y + (size_t)n * Dk);
    float s = 0.f;
    float4 v = xr[threadIdx.x];
    s = v.x * v.x + v.y * v.y + v.z * v.z + v.w * v.w;
    __shared__ float red[8];
    int lane = threadIdx.x & 31, wid = threadIdx.x >> 5;
    #pragma unroll
    for (int o = 16; o; o >>= 1) s += __shfl_xor_sync(0xffffffffu, s, o);
    if (lane == 0) red[wid] = s;
    __syncthreads();
    if (wid == 0) {
        float t = (lane < 8) ? red[lane] : 0.f;
        #pragma unroll
        for (int o = 4; o; o >>= 1) t += __shfl_xor_sync(0xffffffffu, t, o);
        if (lane == 0) red[0] = rsqrtf(t / Dk + EPS);
    }
    __syncthreads();
    float rms = red[0];
    float4 wv = wr[threadIdx.x];
    float4 out;
    out.x = v.x * rms * wv.x;
    out.y = v.y * rms * wv.y;
    out.z = v.z * rms * wv.z;
    out.w = v.w * rms * wv.w;
    yr[threadIdx.x] = out;
}

// ---------------- q/k rmsnorm + rope ----------------
__global__ void qknorm_rope_kernel(float* __restrict__ q, float* __restrict__ k,
                                   const int* __restrict__ positions,
                                   const float* __restrict__ qw, const float* __restrict__ kw)
{
    int n = blockIdx.x;
    int hh = blockIdx.y;
    float* x; const float* w;
    if (hh < Hh) { x = q + ((size_t)n * Hh + hh) * DHd; w = qw; }
    else         { x = k + ((size_t)n * KVh + (hh - Hh)) * DHd; w = kw; }
    int lane = threadIdx.x;
    float x1 = x[lane], x2 = x[lane + 32];
    float s = x1 * x1 + x2 * x2;
    #pragma unroll
    for (int o = 16; o; o >>= 1) s += __shfl_xor_sync(0xffffffffu, s, o);
    float rms = rsqrtf(s / 64.f + EPS);
    float v1 = x1 * rms * w[lane];
    float v2 = x2 * rms * w[lane + 32];
    float inv = (float)exp(-(2.0 * (double)lane / 64.0) * log(10000.0));
    float ang = (float)positions[n] * inv;
    float c = cosf(ang), sn = sinf(ang);
    x[lane]      = v1 * c - v2 * sn;
    x[lane + 32] = v2 * c + v1 * sn;
}

// ---------------- dynamics (elementwise, float4) ----------------
__global__ void dynamics_kernel(const float4* __restrict__ hidden_in,
                                const float4* __restrict__ velocity,
                                const float4* __restrict__ oproj,
                                const float4* __restrict__ mu,
                                const float* __restrict__ co,
                                float4* __restrict__ v_out,
                                float4* __restrict__ hidden2)
{
    int idx = blockIdx.x * blockDim.x + threadIdx.x;
    if (idx >= Nn * Dk / 4) return;
    int n = idx / (Dk / 4), c4 = idx - n * (Dk / 4);
    const float4* cr = (const float4*)(co + (size_t)n * 3 * Dk);
    float4 a_raw  = cr[c4];
    float4 b_raw  = cr[Dk / 4 + c4];
    float4 gt_raw = cr[2 * Dk / 4 + c4];
    float4 ov  = oproj[idx];
    float4 muv = mu[idx];
    float4 vel = velocity[idx];
    float4 hin = hidden_in[idx];
    float4 vn, h2;
    #pragma unroll
    for (int j = 0; j < 4; ++j) {
        float ar = (&a_raw.x)[j], br = (&b_raw.x)[j], gr = (&gt_raw.x)[j];
        float alpha = 1.f / (1.f + expf(-ar));
        float sp = (br > 20.f) ? br : log1pf(expf(br));
        float beta = fminf(sp, 2.f);
        float gate = 1.f / (1.f + expf(-gr));
        float o = (&ov.x)[j];
        float err = o - (&muv.x)[j];
        float vv = alpha * (&vel.x)[j] - beta * err;
        vv = fminf(fmaxf(vv, -10.f), 10.f);
        (&vn.x)[j] = vv;
        (&h2.x)[j] = (&hin.x)[j] + o + DT * gate * vv;
    }
    v_out[idx] = vn;
    hidden2[idx] = h2;
}

// ---------------- router ----------------
__global__ void reset_counts_kernel()
{
    if (threadIdx.x < Ee) g_counts[threadIdx.x] = 0;
}

__global__ void router_kernel(const float* __restrict__ mu, const float* __restrict__ W,
                              const int* __restrict__ token_ids)
{
    int gwarp = (blockIdx.x * blockDim.x + threadIdx.x) >> 5;
    int lane = threadIdx.x & 31;
    if (gwarp >= Nn) return;
    float acc[Ee] = {};
    const float* m = mu + (size_t)gwarp * Dk;
    for (int d = lane; d < Dk; d += 32) {
        float mv = m[d];
        #pragma unroll
        for (int e = 0; e < Ee; ++e) acc[e] += mv * W[d * Ee + e];
    }
    #pragma unroll
    for (int o = 16; o; o >>= 1)
        #pragma unroll
        for (int e = 0; e < Ee; ++e) acc[e] += __shfl_xor_sync(0xffffffffu, acc[e], o);
    if (lane == 0) {
        int base = token_ids[gwarp] % Ee;
        int best = 0; float bv = -1e30f;
        #pragma unroll
        for (int e = 0; e < Ee; ++e) {
            float vv = acc[e] + (e == base ? BASE_SCALE : 0.f);
            if (vv > bv) { bv = vv; best = e; }
        }
        int pos = atomicAdd(&g_counts[best], 1);
        g_list[best * Nn + pos] = gwarp;
    }
}

// ---------------- silu(g)*u elementwise ----------------
__global__ void silumul_kernel(const float4* __restrict__ G, const float4* __restrict__ U,
                               float4* __restrict__ Mid)
{
    int idx = blockIdx.x * blockDim.x + threadIdx.x;
    if (idx >= Nn * Ff / 4) return;
    float4 g = G[idx], u = U[idx], o;
    #pragma unroll
    for (int j = 0; j < 4; ++j) {
        float gv = (&g.x)[j];
        float sg = gv / (1.f + expf(-gv));
        (&o.x)[j] = sg * (&u.x)[j];
    }
    Mid[idx] = o;
}

// ---------------- launch ----------------
static float* sym(const void* s)
{
    void* p = nullptr;
    cudaGetSymbolAddress(&p, s);
    return (float*)p;
}

extern "C" void kernel_launch(void* const* d_in, const int* in_sizes, int n_in,
                              void* d_out, int out_size)
{
    const float* hidden        = (const float*)d_in[0];
    const int*   positions     = (const int*)  d_in[1];
    const float* velocity      = (const float*)d_in[2];
    const int*   token_ids     = (const int*)  d_in[3];
    const float* mu_prev       = (const float*)d_in[4];
    const float* ln1_w         = (const float*)d_in[5];
    const float* ln2_w         = (const float*)d_in[6];
    const float* wq            = (const float*)d_in[7];
    const float* wk            = (const float*)d_in[8];
    const float* wv            = (const float*)d_in[9];
    const float* wo            = (const float*)d_in[10];
    const float* w_mu_q        = (const float*)d_in[11];
    const float* w_mu_k        = (const float*)d_in[12];
    const float* w_mu_v        = (const float*)d_in[13];
    const float* qnorm_w       = (const float*)d_in[14];
    const float* knorm_w       = (const float*)d_in[15];
    const float* dyn_mu        = (const float*)d_in[16];
    const float* dyn_mu_proj_w = (const float*)d_in[17];
    const float* ctrl_in_w     = (const float*)d_in[18];
    const float* ctrl_in_b     = (const float*)d_in[19];
    const float* ctrl_out_w    = (const float*)d_in[20];
    const float* ctrl_out_b    = (const float*)d_in[21];
    const float* mu_router_w   = (const float*)d_in[22];
    const float* w_gate        = (const float*)d_in[23];
    const float* w_up          = (const float*)d_in[24];
    const float* w_down        = (const float*)d_in[25];

    float* out_hidden = (float*)d_out;
    float* out_v      = out_hidden + (size_t)Nn * Dk;
    float* out_mu     = out_v + (size_t)Nn * Dk;

    float* h1   = sym(g_h1);
    float* qb   = sym(g_q);
    float* kb   = sym(g_k);
    float* vb   = sym(g_v);
    float* ob   = sym(g_o);
    float* op   = sym(g_oproj);
    float* ctrl = sym(g_ctrl);
    float* co   = sym(g_co);
    float* h2   = sym(g_hidden2);
    float* x2   = sym(g_x2);
    float* midg = sym(g_midg);
    float* midu = sym(g_midu);
    float* mid  = sym(g_mid);

    // 1) rmsnorm1
    rmsnorm_kernel<<<Nn, 256>>>(hidden, ln1_w, h1);

    // 2) fused QKV = h1@W + mu_prev@W_mu  (tf32 mma, one launch, 192 CTAs)
    qkv_mma_kernel<<<dim3(12, Nn / 128), 256>>>(h1, mu_prev, wq, w_mu_q, wk, w_mu_k,
                                                wv, w_mu_v, qb, kb, vb);

    // 3) q/k norm + rope (in place)
    qknorm_rope_kernel<<<dim3(Nn, Hh + KVh), 32>>>(qb, kb, positions, qnorm_w, knorm_w);

    // 4) attention (tf32 mma v3: register softmax, cp.async K/V)
    attn_mma_kernel<<<dim3(Nn / 64, Hh), 128>>>(qb, kb, vb, ob);

    // 5) o-proj (tf32)
    mma_gemm_kernel<false, false, false, 128, 0><<<dim3(Dk / 128, Nn / 128), 256>>>(
        ob, wo, nullptr, nullptr, nullptr, nullptr, op, Dk, Hh * DHd, Hh * DHd, Dk);

    // 6) mu_cur = dyn_mu + oproj @ dyn_mu_proj_w (tf32, direct to output)
    mma_gemm_kernel<false, false, false, 128, 0><<<dim3(Dk / 128, Nn / 128), 256>>>(
        op, dyn_mu_proj_w, nullptr, nullptr, dyn_mu, nullptr, out_mu, Dk, Dk, Dk, Dk);

    // 7) ctrl = silu([o, velocity] @ ctrl_in_w + b)  (tf32 BN=64, dual, silu)
    mma_gemm_kernel<false, true, false, 64, 1><<<dim3(1, Nn / 128), 256>>>(
        op, ctrl_in_w, velocity, ctrl_in_w + (size_t)Dk * CHc, ctrl_in_b, nullptr,
        ctrl, CHc, Dk, Dk, CHc);

    // 8) co = ctrl @ ctrl_out_w + b  (tf32, K=64)
    mma_gemm_kernel<false, false, false, 128, 0><<<dim3(3 * Dk / 128, Nn / 128), 256>>>(
        ctrl, ctrl_out_w, nullptr, nullptr, ctrl_out_b, nullptr, co, 3 * Dk, CHc, CHc, 3 * Dk);

    // 9) dynamics: v_next (output), hidden2
    dynamics_kernel<<<(Nn * Dk / 4 + 255) / 256, 256>>>((const float4*)hidden, (const float4*)velocity,
                                                        (const float4*)op, (const float4*)out_mu, co,
                                                        (float4*)out_v, (float4*)h2);

    // 10) rmsnorm2
    rmsnorm_kernel<<<Nn, 256>>>(h2, ln2_w, x2);

    // 11) router
    reset_counts_kernel<<<1, 32>>>();
    router_kernel<<<(Nn * 32 + 255) / 256, 256>>>(out_mu, mu_router_w, token_ids);

    // 12) MoE gate & up (tf32, gathered)
    mma_gemm_kernel<true, false, false, 128, 0><<<dim3(Ff / 128, Nn / 128, Ee), 256>>>(
        x2, w_gate, nullptr, nullptr, nullptr, nullptr, midg, Ff, Dk, Dk, Ff);
    mma_gemm_kernel<true, false, false, 128, 0><<<dim3(Ff / 128, Nn / 128, Ee), 256>>>(
        x2, w_up, nullptr, nullptr, nullptr, nullptr, midu, Ff, Dk, Dk, Ff);

    // 12b) mid = silu(g) * u
    silumul_kernel<<<(Nn * Ff / 4 + 255) / 256, 256>>>((const float4*)midg, (const float4*)midu,
                                                       (float4*)mid);

    // 13) MoE down + residual -> final hidden (tf32, gathered)
    mma_gemm_kernel<true, false, true, 128, 0><<<dim3(Dk / 128, Nn / 128, Ee), 256>>>(
        mid, w_down, nullptr, nullptr, nullptr, h2, out_hidden, Dk, Ff, Ff, Dk);
}